// round 4
// baseline (speedup 1.0000x reference)
#include <cuda_runtime.h>
#include <cuda_bf16.h>
#include <math.h>
#include <stdint.h>

// Problem shapes (fixed by the reference)
#define BB      2
#define LL      1024
#define DIM     1024
#define DI      2048          // d_inner
#define MROWS   (BB*LL)       // 2048
#define DTRANK  64
#define DSTATE  16
#define XPROJ_N (DTRANK + 2*DSTATE)  // 96
#define NSPLIT  8

typedef __nv_bfloat16 bf16;

// ---------------- scratch (device globals; no allocation allowed) ----------
__device__ float g_xz  [MROWS * 2 * DI];
__device__ float g_u   [MROWS * DI];
__device__ float g_xdbl[MROWS * XPROJ_N];
__device__ float g_dt  [MROWS * DI];
__device__ float g_part[NSPLIT * MROWS * XPROJ_N];

__device__ bf16 g_xnh [MROWS * DIM],   g_xnl [MROWS * DIM];
__device__ bf16 g_winh[2*DI * DIM],    g_winl[2*DI * DIM];
__device__ bf16 g_yh  [MROWS * DI],    g_yl  [MROWS * DI];
__device__ bf16 g_woh [DIM * DI],      g_wol [DIM * DI];
__device__ bf16 g_dtrh[MROWS * DTRANK],g_dtrl[MROWS * DTRANK];
__device__ bf16 g_wdth[DI * DTRANK],   g_wdtl[DI * DTRANK];

// =================== baseline PTX helpers (no arch-'a' features) ============
__device__ __forceinline__ uint32_t smem_u32(const void* p) {
    uint32_t a;
    asm("{ .reg .u64 t; cvta.to.shared.u64 t, %1; cvt.u32.u64 %0, t; }" : "=r"(a) : "l"(p));
    return a;
}
#define CP_ASYNC16(dst, src) \
    asm volatile("cp.async.cg.shared.global [%0], [%1], 16;" :: "r"(dst), "l"(src))
#define CP_COMMIT() asm volatile("cp.async.commit_group;" ::: "memory")
#define CP_WAIT(n)  asm volatile("cp.async.wait_group %0;" :: "n"(n) : "memory")
#define CP_WAIT_DYN(n) do { \
    if ((n) >= 2) CP_WAIT(2); else if ((n) == 1) CP_WAIT(1); else CP_WAIT(0); } while (0)

__device__ __forceinline__ void ldsm4(uint32_t* r, uint32_t addr) {
    asm volatile("ldmatrix.sync.aligned.m8n8.x4.shared.b16 {%0,%1,%2,%3}, [%4];"
                 : "=r"(r[0]), "=r"(r[1]), "=r"(r[2]), "=r"(r[3]) : "r"(addr));
}
__device__ __forceinline__ void mma_bf16(float* c, const uint32_t* a, const uint32_t* b) {
    asm volatile("mma.sync.aligned.m16n8k16.row.col.f32.bf16.bf16.f32 "
                 "{%0,%1,%2,%3}, {%4,%5,%6,%7}, {%8,%9}, {%0,%1,%2,%3};"
                 : "+f"(c[0]), "+f"(c[1]), "+f"(c[2]), "+f"(c[3])
                 : "r"(a[0]), "r"(a[1]), "r"(a[2]), "r"(a[3]), "r"(b[0]), "r"(b[1]));
}
// SW64 swizzle for 64-byte stage rows
__device__ __forceinline__ uint32_t sw64(uint32_t off) { return off ^ ((off >> 3) & 0x30); }

__device__ __forceinline__ void split_bf16(float x, bf16& h, bf16& l) {
    h = __float2bfloat16(x);
    l = __float2bfloat16(x - __bfloat162float(h));
}

// =================== bf16x2 mma.sync GEMM: C = A @ B^T ======================
// BM=128, BN=128, BK=32/stage, 4-stage cp.async ring, 8 warps.
// EPI: 0 none, 1 softplus+bias, 2 +resid
template<int EPI>
__global__ void __launch_bounds__(256, 1)
gemm_bf16x2(const bf16* __restrict__ Ah, const bf16* __restrict__ Al,
            const bf16* __restrict__ Bh, const bf16* __restrict__ Bl,
            float* __restrict__ C, const float* __restrict__ aux,
            int K, int ldc) {
    extern __shared__ char smem[];
    const uint32_t sb = smem_u32(smem);
    const int STG = 32768;               // 4 mats x 8KB per stage
    const int tid = threadIdx.x, wid = tid >> 5, lane = tid & 31;
    const int m0 = blockIdx.y * 128, n0 = blockIdx.x * 128;
    const int wm = wid >> 2, wn = wid & 3;   // warp tile: 64(M) x 32(N)

    float acc[4][4][4];
    #pragma unroll
    for (int a = 0; a < 4; a++)
        #pragma unroll
        for (int b = 0; b < 4; b++)
            #pragma unroll
            for (int c = 0; c < 4; c++) acc[a][b][c] = 0.f;

    const bf16* srcs[4] = {Ah, Al, Bh, Bl};

    // one stage: 4 matrices x 128 rows x 32 bf16 (64B rows, SW64)
    auto load_stage = [&](int s, int kc) {
        uint32_t base = sb + s * STG;
        #pragma unroll
        for (int mtx = 0; mtx < 4; mtx++) {
            const bf16* S = srcs[mtx];
            int row0 = (mtx < 2) ? m0 : n0;
            uint32_t dbase = base + mtx * 8192;
            #pragma unroll
            for (int it = 0; it < 2; it++) {
                int i = tid + it * 256;          // 512 16B-units
                int row = i >> 2, j = i & 3;
                uint32_t dst = dbase + sw64(row * 64 + j * 16);
                const void* src = S + (size_t)(row0 + row) * K + kc * 32 + j * 8;
                CP_ASYNC16(dst, src);
            }
        }
        CP_COMMIT();
    };

    auto compute = [&](int s) {
        uint32_t pAh = sb + s * STG, pAl = pAh + 8192;
        uint32_t pBh = pAl + 8192,   pBl = pBh + 8192;
        #pragma unroll
        for (int kk = 0; kk < 2; kk++) {
            uint32_t ah[4][4], al[4][4], bh[2][4], bl[2][4];
            int kbA = kk * 32 + ((lane >> 4) << 4);
            #pragma unroll
            for (int mt = 0; mt < 4; mt++) {
                int row = wm * 64 + mt * 16 + (lane & 15);
                uint32_t off = sw64(row * 64 + kbA);
                ldsm4(ah[mt], pAh + off);
                ldsm4(al[mt], pAl + off);
            }
            // B: x4 = two n8-tiles per ldmatrix
            int grp = lane >> 3, l8 = lane & 7;
            int kbB = kk * 32 + ((grp & 1) << 4);
            #pragma unroll
            for (int pr = 0; pr < 2; pr++) {
                int row = wn * 32 + pr * 16 + ((grp >> 1) << 3) + l8;
                uint32_t off = sw64(row * 64 + kbB);
                ldsm4(bh[pr], pBh + off);
                ldsm4(bl[pr], pBl + off);
            }
            #pragma unroll
            for (int mt = 0; mt < 4; mt++)
                #pragma unroll
                for (int pr = 0; pr < 2; pr++)
                    #pragma unroll
                    for (int half = 0; half < 2; half++) {
                        int nt = pr * 2 + half;
                        mma_bf16(acc[mt][nt], ah[mt], &bh[pr][half * 2]);
                        mma_bf16(acc[mt][nt], ah[mt], &bl[pr][half * 2]);
                        mma_bf16(acc[mt][nt], al[mt], &bh[pr][half * 2]);
                    }
        }
    };

    const int nst = K >> 5;
    const int npro = (nst < 3) ? nst : 3;
    for (int p = 0; p < npro; p++) load_stage(p & 3, p);
    for (int kc = 0; kc < nst; kc++) {
        int rem = nst - 1 - kc;
        CP_WAIT_DYN(rem < 2 ? rem : 2);
        __syncthreads();
        if (kc + 3 < nst) load_stage((kc + 3) & 3, kc + 3);
        compute(kc & 3);
    }

    // epilogue: write fp32 directly from fragments
    #pragma unroll
    for (int mt = 0; mt < 4; mt++) {
        #pragma unroll
        for (int nt = 0; nt < 4; nt++) {
            int row = m0 + wm * 64 + mt * 16 + (lane >> 2);
            int col = n0 + wn * 32 + nt * 8 + (lane & 3) * 2;
            float v[4] = {acc[mt][nt][0], acc[mt][nt][1], acc[mt][nt][2], acc[mt][nt][3]};
            if (EPI == 1) {
                #pragma unroll
                for (int i = 0; i < 4; i++) {
                    float t = v[i] + aux[col + (i & 1)];
                    v[i] = fmaxf(t, 0.f) + log1pf(__expf(-fabsf(t)));
                }
            } else if (EPI == 2) {
                v[0] += aux[(size_t)row * ldc + col];
                v[1] += aux[(size_t)row * ldc + col + 1];
                v[2] += aux[(size_t)(row + 8) * ldc + col];
                v[3] += aux[(size_t)(row + 8) * ldc + col + 1];
            }
            *reinterpret_cast<float2*>(&C[(size_t)row * ldc + col])       = make_float2(v[0], v[1]);
            *reinterpret_cast<float2*>(&C[(size_t)(row + 8) * ldc + col]) = make_float2(v[2], v[3]);
        }
    }
}

// ---------------- conversion kernels ---------------------------------------
__global__ void cvt_hilo(const float* __restrict__ s, bf16* __restrict__ h,
                         bf16* __restrict__ l, int n4) {
    int i = blockIdx.x * blockDim.x + threadIdx.x;
    if (i >= n4) return;
    float4 v = reinterpret_cast<const float4*>(s)[i];
    bf16 h0, h1, h2, h3, l0, l1, l2, l3;
    split_bf16(v.x, h0, l0); split_bf16(v.y, h1, l1);
    split_bf16(v.z, h2, l2); split_bf16(v.w, h3, l3);
    __nv_bfloat162* h2p = reinterpret_cast<__nv_bfloat162*>(h);
    __nv_bfloat162* l2p = reinterpret_cast<__nv_bfloat162*>(l);
    h2p[i*2]   = __nv_bfloat162(h0, h1);
    h2p[i*2+1] = __nv_bfloat162(h2, h3);
    l2p[i*2]   = __nv_bfloat162(l0, l1);
    l2p[i*2+1] = __nv_bfloat162(l2, l3);
}

__global__ void cvt_dtr(const float* __restrict__ xdbl, bf16* __restrict__ h,
                        bf16* __restrict__ l) {
    int i = blockIdx.x * blockDim.x + threadIdx.x;
    if (i >= MROWS * DTRANK / 4) return;
    int row = i >> 4, c4 = (i & 15) * 4;
    float4 v = *reinterpret_cast<const float4*>(&xdbl[(size_t)row * XPROJ_N + c4]);
    bf16 h0, h1, h2, h3, l0, l1, l2, l3;
    split_bf16(v.x, h0, l0); split_bf16(v.y, h1, l1);
    split_bf16(v.z, h2, l2); split_bf16(v.w, h3, l3);
    __nv_bfloat162* h2p = reinterpret_cast<__nv_bfloat162*>(h + (size_t)row * DTRANK + c4);
    __nv_bfloat162* l2p = reinterpret_cast<__nv_bfloat162*>(l + (size_t)row * DTRANK + c4);
    h2p[0] = __nv_bfloat162(h0, h1); h2p[1] = __nv_bfloat162(h2, h3);
    l2p[0] = __nv_bfloat162(l0, l1); l2p[1] = __nv_bfloat162(l2, l3);
}

// ---------------- LayerNorm (fused hi/lo split output) ----------------------
__global__ void ln_kernel(const float* __restrict__ x,
                          const float* __restrict__ w,
                          const float* __restrict__ b,
                          bf16* __restrict__ xnh, bf16* __restrict__ xnl) {
    int row = blockIdx.x;
    int tid = threadIdx.x;
    const float4* xr = reinterpret_cast<const float4*>(x + row * DIM);
    float4 v = xr[tid];
    float s  = v.x + v.y + v.z + v.w;
    float sq = v.x*v.x + v.y*v.y + v.z*v.z + v.w*v.w;
    __shared__ float red[2][8];
    for (int off = 16; off > 0; off >>= 1) {
        s  += __shfl_xor_sync(0xffffffffu, s,  off);
        sq += __shfl_xor_sync(0xffffffffu, sq, off);
    }
    int warp = tid >> 5, lane = tid & 31;
    if (lane == 0) { red[0][warp] = s; red[1][warp] = sq; }
    __syncthreads();
    if (warp == 0) {
        float a = (lane < 8) ? red[0][lane] : 0.f;
        float c = (lane < 8) ? red[1][lane] : 0.f;
        for (int off = 4; off > 0; off >>= 1) {
            a += __shfl_xor_sync(0xffffffffu, a, off);
            c += __shfl_xor_sync(0xffffffffu, c, off);
        }
        if (lane == 0) { red[0][0] = a; red[1][0] = c; }
    }
    __syncthreads();
    float mu  = red[0][0] * (1.f / DIM);
    float var = red[1][0] * (1.f / DIM) - mu * mu;
    float rs  = rsqrtf(var + 1e-5f);
    const float4* w4 = reinterpret_cast<const float4*>(w);
    const float4* b4 = reinterpret_cast<const float4*>(b);
    float4 ww = w4[tid], bb = b4[tid];
    float o0 = (v.x - mu) * rs * ww.x + bb.x;
    float o1 = (v.y - mu) * rs * ww.y + bb.y;
    float o2 = (v.z - mu) * rs * ww.z + bb.z;
    float o3 = (v.w - mu) * rs * ww.w + bb.w;
    bf16 h0, h1, h2, h3, l0, l1, l2, l3;
    split_bf16(o0, h0, l0); split_bf16(o1, h1, l1);
    split_bf16(o2, h2, l2); split_bf16(o3, h3, l3);
    __nv_bfloat162* hp = reinterpret_cast<__nv_bfloat162*>(xnh + (size_t)row * DIM + tid * 4);
    __nv_bfloat162* lp = reinterpret_cast<__nv_bfloat162*>(xnl + (size_t)row * DIM + tid * 4);
    hp[0] = __nv_bfloat162(h0, h1); hp[1] = __nv_bfloat162(h2, h3);
    lp[0] = __nv_bfloat162(l0, l1); lp[1] = __nv_bfloat162(l2, l3);
}

// ---------------- xproj split-K: partial + reduce ---------------------------
__global__ void xproj_partial(const float* __restrict__ Au, const float* __restrict__ W,
                              float* __restrict__ part) {
    __shared__ float As[32][33];
    __shared__ float Ws[32][97];
    int tid = threadIdx.x;
    int m0 = blockIdx.x * 32;
    int split = blockIdx.y;
    int kbase = split * (DI / NSPLIT);
    int tx = tid & 15, ty = tid >> 4;
    float acc[2][6];
    #pragma unroll
    for (int i = 0; i < 2; i++)
        #pragma unroll
        for (int j = 0; j < 6; j++) acc[i][j] = 0.f;

    for (int k0 = 0; k0 < DI / NSPLIT; k0 += 32) {
        {
            int row = tid >> 3, j = tid & 7;
            float4 v = *reinterpret_cast<const float4*>(&Au[(size_t)(m0 + row) * DI + kbase + k0 + j * 4]);
            As[j*4+0][row] = v.x; As[j*4+1][row] = v.y;
            As[j*4+2][row] = v.z; As[j*4+3][row] = v.w;
        }
        #pragma unroll
        for (int it = 0; it < 3; it++) {
            int i = tid + it * 256;
            int row = i >> 3, j = i & 7;
            float4 v = *reinterpret_cast<const float4*>(&W[(size_t)row * DI + kbase + k0 + j * 4]);
            Ws[j*4+0][row] = v.x; Ws[j*4+1][row] = v.y;
            Ws[j*4+2][row] = v.z; Ws[j*4+3][row] = v.w;
        }
        __syncthreads();
        #pragma unroll
        for (int kk = 0; kk < 32; kk++) {
            float a0 = As[kk][ty * 2 + 0], a1 = As[kk][ty * 2 + 1];
            float w[6];
            #pragma unroll
            for (int j = 0; j < 6; j++) w[j] = Ws[kk][tx * 6 + j];
            #pragma unroll
            for (int j = 0; j < 6; j++) {
                acc[0][j] = fmaf(a0, w[j], acc[0][j]);
                acc[1][j] = fmaf(a1, w[j], acc[1][j]);
            }
        }
        __syncthreads();
    }
    float* dst = part + (size_t)split * MROWS * XPROJ_N;
    #pragma unroll
    for (int i = 0; i < 2; i++)
        #pragma unroll
        for (int j = 0; j < 6; j++)
            dst[(size_t)(m0 + ty * 2 + i) * XPROJ_N + tx * 6 + j] = acc[i][j];
}

__global__ void xproj_reduce(const float* __restrict__ part, float* __restrict__ xdbl) {
    int i = blockIdx.x * blockDim.x + threadIdx.x;
    const int TOT4 = MROWS * XPROJ_N / 4;
    if (i >= TOT4) return;
    float4 s = reinterpret_cast<const float4*>(part)[i];
    #pragma unroll
    for (int sp = 1; sp < NSPLIT; sp++) {
        float4 v = reinterpret_cast<const float4*>(part + (size_t)sp * MROWS * XPROJ_N)[i];
        s.x += v.x; s.y += v.y; s.z += v.z; s.w += v.w;
    }
    reinterpret_cast<float4*>(xdbl)[i] = s;
}

// ---------------- causal depthwise conv (k=4) + SiLU ------------------------
__global__ void conv_silu_kernel(const float* __restrict__ xz,
                                 const float* __restrict__ cw,
                                 const float* __restrict__ cb,
                                 float* __restrict__ u) {
    int idx = blockIdx.x * blockDim.x + threadIdx.x;
    if (idx >= BB * LL * DI) return;
    int e = idx & (DI - 1);
    int l = (idx >> 11) & (LL - 1);
    int b = idx >> 21;
    float acc = cb[e];
    #pragma unroll
    for (int k = 0; k < 4; k++) {
        int ls = l + k - 3;
        if (ls >= 0)
            acc = fmaf(cw[e * 4 + k], xz[((size_t)(b * LL + ls)) * (2 * DI) + e], acc);
    }
    float s = acc / (1.f + __expf(-acc));
    u[(size_t)(b * LL + l) * DI + e] = s;
}

// ---------------- SSM selective scan (writes y as hi/lo bf16) ---------------
#define CHUNK 64
__global__ void scan_kernel(const float* __restrict__ dt,
                            const float* __restrict__ u,
                            const float* __restrict__ xdbl,
                            const float* __restrict__ xz,
                            const float* __restrict__ a_log,
                            const float* __restrict__ d_skip,
                            bf16* __restrict__ yh, bf16* __restrict__ yl) {
    __shared__ float sB [CHUNK][DSTATE];
    __shared__ float sC [CHUNK][DSTATE];
    __shared__ float sDt[CHUNK][16];
    __shared__ float sU [CHUNK][16];
    __shared__ float sZ [CHUNK][16];
    int tid  = threadIdx.x;
    int g    = tid >> 4;
    int lane = tid & 15;
    int c0   = blockIdx.x * 16;
    int b    = c0 >> 11;
    int e0   = c0 & (DI - 1);
    int e    = e0 + g;
    float A_n = -__expf(a_log[e * DSTATE + lane]);
    float dsk = d_skip[e];
    float h = 0.f;
    int rowbase = b * LL;
    for (int l0 = 0; l0 < LL; l0 += CHUNK) {
        __syncthreads();
        for (int i = tid; i < CHUNK * 2 * DSTATE; i += 256) {
            int r = i >> 5, j = i & 31;
            float v = xdbl[(size_t)(rowbase + l0 + r) * XPROJ_N + DTRANK + j];
            if (j < DSTATE) sB[r][j] = v; else sC[r][j - DSTATE] = v;
        }
        for (int i = tid; i < CHUNK * 16; i += 256) {
            int r = i >> 4, j = i & 15;
            size_t m = (size_t)(rowbase + l0 + r);
            sDt[r][j] = dt[m * DI + e0 + j];
            sU [r][j] = u [m * DI + e0 + j];
            sZ [r][j] = xz[m * (2 * DI) + DI + e0 + j];
        }
        __syncthreads();
        #pragma unroll 4
        for (int r = 0; r < CHUNK; r++) {
            float dtv = sDt[r][g];
            float uv  = sU [r][g];
            float dA  = __expf(dtv * A_n);
            float dBu = dtv * sB[r][lane] * uv;
            h = fmaf(dA, h, dBu);
            float yv = h * sC[r][lane];
            yv += __shfl_xor_sync(0xffffffffu, yv, 8);
            yv += __shfl_xor_sync(0xffffffffu, yv, 4);
            yv += __shfl_xor_sync(0xffffffffu, yv, 2);
            yv += __shfl_xor_sync(0xffffffffu, yv, 1);
            if (lane == 0) {
                float zv = sZ[r][g];
                float sz = zv / (1.f + __expf(-zv));
                float yo = (yv + uv * dsk) * sz;
                bf16 hh, ll;
                split_bf16(yo, hh, ll);
                size_t o = (size_t)(rowbase + l0 + r) * DI + e;
                yh[o] = hh; yl[o] = ll;
            }
        }
    }
}

// ---------------- launch -----------------------------------------------------
extern "C" void kernel_launch(void* const* d_in, const int* in_sizes, int n_in,
                              void* d_out, int out_size) {
    const float* x      = (const float*)d_in[0];
    const float* ln_w   = (const float*)d_in[1];
    const float* ln_b   = (const float*)d_in[2];
    const float* w_in   = (const float*)d_in[3];
    const float* conv_w = (const float*)d_in[4];
    const float* conv_b = (const float*)d_in[5];
    const float* w_xpr  = (const float*)d_in[6];
    const float* w_dt   = (const float*)d_in[7];
    const float* b_dt   = (const float*)d_in[8];
    const float* a_log  = (const float*)d_in[9];
    const float* d_skip = (const float*)d_in[10];
    const float* w_out  = (const float*)d_in[11];
    float* out = (float*)d_out;

    float *xz, *u, *xdbl, *dt, *part;
    bf16 *xnh, *xnl, *winh, *winl, *yh, *yl, *woh, *wol, *dtrh, *dtrl, *wdth, *wdtl;
    cudaGetSymbolAddress((void**)&xz,   g_xz);
    cudaGetSymbolAddress((void**)&u,    g_u);
    cudaGetSymbolAddress((void**)&xdbl, g_xdbl);
    cudaGetSymbolAddress((void**)&dt,   g_dt);
    cudaGetSymbolAddress((void**)&part, g_part);
    cudaGetSymbolAddress((void**)&xnh,  g_xnh);
    cudaGetSymbolAddress((void**)&xnl,  g_xnl);
    cudaGetSymbolAddress((void**)&winh, g_winh);
    cudaGetSymbolAddress((void**)&winl, g_winl);
    cudaGetSymbolAddress((void**)&yh,   g_yh);
    cudaGetSymbolAddress((void**)&yl,   g_yl);
    cudaGetSymbolAddress((void**)&woh,  g_woh);
    cudaGetSymbolAddress((void**)&wol,  g_wol);
    cudaGetSymbolAddress((void**)&dtrh, g_dtrh);
    cudaGetSymbolAddress((void**)&dtrl, g_dtrl);
    cudaGetSymbolAddress((void**)&wdth, g_wdth);
    cudaGetSymbolAddress((void**)&wdtl, g_wdtl);

    const int SMEM_GT = 4 * 32768;   // 128 KB, 4-stage ring
    cudaFuncSetAttribute(gemm_bf16x2<0>, cudaFuncAttributeMaxDynamicSharedMemorySize, SMEM_GT);
    cudaFuncSetAttribute(gemm_bf16x2<1>, cudaFuncAttributeMaxDynamicSharedMemorySize, SMEM_GT);
    cudaFuncSetAttribute(gemm_bf16x2<2>, cudaFuncAttributeMaxDynamicSharedMemorySize, SMEM_GT);

    // launch order arranged so the ncu capture window lands on gemm1
    // 1. w_in conversion
    cvt_hilo<<<(2*DI*DIM/4 + 255)/256, 256>>>(w_in,  winh, winl, 2*DI*DIM/4);
    // 2. LayerNorm (+ hi/lo split)
    ln_kernel<<<MROWS, 256>>>(x, ln_w, ln_b, xnh, xnl);
    // 3. w_out conversion
    cvt_hilo<<<(DIM*DI/4 + 255)/256, 256>>>(w_out, woh,  wol,  DIM*DI/4);
    // 4. xz = xn @ w_in^T   (2048 x 4096 x 1024)  [bf16x2 mma]
    gemm_bf16x2<0><<<dim3(4096/128, MROWS/128), 256, SMEM_GT>>>(
        xnh, xnl, winh, winl, xz, nullptr, DIM, 2*DI);
    // 5. u = silu(conv(xs))
    conv_silu_kernel<<<(BB*LL*DI)/256, 256>>>(xz, conv_w, conv_b, u);
    // 6. w_dt conversion
    cvt_hilo<<<(DI*DTRANK/4 + 255)/256, 256>>>(w_dt, wdth, wdtl, DI*DTRANK/4);
    // 7-8. x_dbl = u @ w_xproj^T  (2048 x 96 x 2048)  [split-K fp32]
    xproj_partial<<<dim3(MROWS/32, NSPLIT), 256>>>(u, w_xpr, part);
    xproj_reduce<<<(MROWS*XPROJ_N/4 + 255)/256, 256>>>(part, xdbl);
    // 9. dt_r hi/lo extract
    cvt_dtr<<<(MROWS*DTRANK/4 + 255)/256, 256>>>(xdbl, dtrh, dtrl);
    // 10. dt = softplus(dt_r @ w_dt^T + b_dt)  (2048 x 2048 x 64)  [bf16x2 mma]
    gemm_bf16x2<1><<<dim3(DI/128, MROWS/128), 256, SMEM_GT>>>(
        dtrh, dtrl, wdth, wdtl, dt, b_dt, DTRANK, DI);
    // 11. selective scan (+ skip + gate, hi/lo split output)
    scan_kernel<<<(BB*DI)/16, 256>>>(dt, u, xdbl, xz, a_log, d_skip, yh, yl);
    // 12. out = residual + y @ w_out^T  (2048 x 1024 x 2048)  [bf16x2 mma]
    gemm_bf16x2<2><<<dim3(DIM/128, MROWS/128), 256, SMEM_GT>>>(
        yh, yl, woh, wol, out, x, DI, DIM);
}

// round 5
// speedup vs baseline: 1.5948x; 1.5948x over previous
#include <cuda_runtime.h>
#include <cuda_bf16.h>
#include <math.h>
#include <stdint.h>

// Problem shapes (fixed by the reference)
#define BB      2
#define LL      1024
#define DIM     1024
#define DI      2048          // d_inner
#define MROWS   (BB*LL)       // 2048
#define DTRANK  64
#define DSTATE  16
#define XPROJ_N (DTRANK + 2*DSTATE)  // 96
#define NSPLIT  8

typedef __nv_bfloat16 bf16;

// ---------------- scratch (device globals; no allocation allowed) ----------
__device__ float g_xz  [MROWS * 2 * DI];
__device__ float g_u   [MROWS * DI];
__device__ float g_xdbl[MROWS * XPROJ_N];
__device__ float g_dt  [MROWS * DI];
__device__ float g_part[NSPLIT * MROWS * XPROJ_N];

__device__ bf16 g_xnh [MROWS * DIM],   g_xnl [MROWS * DIM];
__device__ bf16 g_winh[2*DI * DIM],    g_winl[2*DI * DIM];
__device__ bf16 g_yh  [MROWS * DI],    g_yl  [MROWS * DI];
__device__ bf16 g_woh [DIM * DI],      g_wol [DIM * DI];
__device__ bf16 g_dtrh[MROWS * DTRANK],g_dtrl[MROWS * DTRANK];
__device__ bf16 g_wdth[DI * DTRANK],   g_wdtl[DI * DTRANK];

// =================== baseline PTX helpers (no arch-'a' features) ============
__device__ __forceinline__ uint32_t smem_u32(const void* p) {
    uint32_t a;
    asm("{ .reg .u64 t; cvta.to.shared.u64 t, %1; cvt.u32.u64 %0, t; }" : "=r"(a) : "l"(p));
    return a;
}
#define CP_ASYNC16(dst, src) \
    asm volatile("cp.async.cg.shared.global [%0], [%1], 16;" :: "r"(dst), "l"(src))
#define CP_COMMIT() asm volatile("cp.async.commit_group;" ::: "memory")
#define CP_WAIT(n)  asm volatile("cp.async.wait_group %0;" :: "n"(n) : "memory")

__device__ __forceinline__ void ldsm4(uint32_t* r, uint32_t addr) {
    asm volatile("ldmatrix.sync.aligned.m8n8.x4.shared.b16 {%0,%1,%2,%3}, [%4];"
                 : "=r"(r[0]), "=r"(r[1]), "=r"(r[2]), "=r"(r[3]) : "r"(addr));
}
__device__ __forceinline__ void mma_bf16(float* c, const uint32_t* a, const uint32_t* b) {
    asm volatile("mma.sync.aligned.m16n8k16.row.col.f32.bf16.bf16.f32 "
                 "{%0,%1,%2,%3}, {%4,%5,%6,%7}, {%8,%9}, {%0,%1,%2,%3};"
                 : "+f"(c[0]), "+f"(c[1]), "+f"(c[2]), "+f"(c[3])
                 : "r"(a[0]), "r"(a[1]), "r"(a[2]), "r"(a[3]), "r"(b[0]), "r"(b[1]));
}
// SW64 swizzle for 64-byte stage rows (verified conflict-free for ldsm phases)
__device__ __forceinline__ uint32_t sw64(uint32_t off) { return off ^ ((off >> 3) & 0x30); }

__device__ __forceinline__ void split_bf16(float x, bf16& h, bf16& l) {
    h = __float2bfloat16(x);
    l = __float2bfloat16(x - __bfloat162float(h));
}

// =================== bf16x2 mma.sync GEMM: C = A @ B^T ======================
// BM=128, BN=128, BK=32/stage, 2-stage cp.async double buffer, 8 warps,
// 2 CTAs/SM (64KB smem, <=128 regs). EPI: 0 none, 1 softplus+bias, 2 +resid
template<int EPI>
__global__ void __launch_bounds__(256, 2)
gemm_bf16x2(const bf16* __restrict__ Ah, const bf16* __restrict__ Al,
            const bf16* __restrict__ Bh, const bf16* __restrict__ Bl,
            float* __restrict__ C, const float* __restrict__ aux,
            int K, int ldc) {
    extern __shared__ char smem[];
    const uint32_t sb = smem_u32(smem);
    const int STG = 32768;               // 4 mats x 8KB per stage
    const int tid = threadIdx.x, wid = tid >> 5, lane = tid & 31;
    const int m0 = blockIdx.y * 128, n0 = blockIdx.x * 128;
    const int wm = wid >> 2, wn = wid & 3;   // warp tile: 64(M) x 32(N)

    float acc[4][4][4];
    #pragma unroll
    for (int a = 0; a < 4; a++)
        #pragma unroll
        for (int b = 0; b < 4; b++)
            #pragma unroll
            for (int c = 0; c < 4; c++) acc[a][b][c] = 0.f;

    const bf16* srcs[4] = {Ah, Al, Bh, Bl};

    // one stage: 4 matrices x 128 rows x 32 bf16 (64B rows, SW64)
    auto load_stage = [&](int s, int kc) {
        uint32_t base = sb + s * STG;
        #pragma unroll
        for (int mtx = 0; mtx < 4; mtx++) {
            const bf16* S = srcs[mtx];
            int row0 = (mtx < 2) ? m0 : n0;
            uint32_t dbase = base + mtx * 8192;
            #pragma unroll
            for (int it = 0; it < 2; it++) {
                int i = tid + it * 256;          // 512 16B-units
                int row = i >> 2, j = i & 3;
                uint32_t dst = dbase + sw64(row * 64 + j * 16);
                const void* src = S + (size_t)(row0 + row) * K + kc * 32 + j * 8;
                CP_ASYNC16(dst, src);
            }
        }
        CP_COMMIT();
    };

    // register-lean compute: B frags resident, A frags streamed per m-tile
    auto compute = [&](int s) {
        uint32_t pAh = sb + s * STG, pAl = pAh + 8192;
        uint32_t pBh = pAl + 8192,   pBl = pBh + 8192;
        #pragma unroll
        for (int kk = 0; kk < 2; kk++) {
            uint32_t bh[2][4], bl[2][4];
            int grp = lane >> 3, l8 = lane & 7;
            int kbB = kk * 32 + ((grp & 1) << 4);
            #pragma unroll
            for (int pr = 0; pr < 2; pr++) {
                int row = wn * 32 + pr * 16 + ((grp >> 1) << 3) + l8;
                uint32_t off = sw64(row * 64 + kbB);
                ldsm4(bh[pr], pBh + off);
                ldsm4(bl[pr], pBl + off);
            }
            int kbA = kk * 32 + ((lane >> 4) << 4);
            #pragma unroll
            for (int mt = 0; mt < 4; mt++) {
                uint32_t ah[4], al[4];
                int row = wm * 64 + mt * 16 + (lane & 15);
                uint32_t off = sw64(row * 64 + kbA);
                ldsm4(ah, pAh + off);
                ldsm4(al, pAl + off);
                #pragma unroll
                for (int pr = 0; pr < 2; pr++)
                    #pragma unroll
                    for (int half = 0; half < 2; half++) {
                        int nt = pr * 2 + half;
                        mma_bf16(acc[mt][nt], ah, &bh[pr][half * 2]);
                        mma_bf16(acc[mt][nt], ah, &bl[pr][half * 2]);
                        mma_bf16(acc[mt][nt], al, &bh[pr][half * 2]);
                    }
            }
        }
    };

    const int nst = K >> 5;
    load_stage(0, 0);
    for (int kc = 0; kc < nst; kc++) {
        if (kc + 1 < nst) { load_stage((kc + 1) & 1, kc + 1); CP_WAIT(1); }
        else              { CP_WAIT(0); }
        __syncthreads();
        compute(kc & 1);
        __syncthreads();
    }

    // epilogue: write fp32 directly from fragments
    #pragma unroll
    for (int mt = 0; mt < 4; mt++) {
        #pragma unroll
        for (int nt = 0; nt < 4; nt++) {
            int row = m0 + wm * 64 + mt * 16 + (lane >> 2);
            int col = n0 + wn * 32 + nt * 8 + (lane & 3) * 2;
            float v[4] = {acc[mt][nt][0], acc[mt][nt][1], acc[mt][nt][2], acc[mt][nt][3]};
            if (EPI == 1) {
                #pragma unroll
                for (int i = 0; i < 4; i++) {
                    float t = v[i] + aux[col + (i & 1)];
                    v[i] = fmaxf(t, 0.f) + log1pf(__expf(-fabsf(t)));
                }
            } else if (EPI == 2) {
                v[0] += aux[(size_t)row * ldc + col];
                v[1] += aux[(size_t)row * ldc + col + 1];
                v[2] += aux[(size_t)(row + 8) * ldc + col];
                v[3] += aux[(size_t)(row + 8) * ldc + col + 1];
            }
            *reinterpret_cast<float2*>(&C[(size_t)row * ldc + col])       = make_float2(v[0], v[1]);
            *reinterpret_cast<float2*>(&C[(size_t)(row + 8) * ldc + col]) = make_float2(v[2], v[3]);
        }
    }
}

// ---------------- conversion kernels ---------------------------------------
__global__ void cvt_hilo(const float* __restrict__ s, bf16* __restrict__ h,
                         bf16* __restrict__ l, int n4) {
    int i = blockIdx.x * blockDim.x + threadIdx.x;
    if (i >= n4) return;
    float4 v = reinterpret_cast<const float4*>(s)[i];
    bf16 h0, h1, h2, h3, l0, l1, l2, l3;
    split_bf16(v.x, h0, l0); split_bf16(v.y, h1, l1);
    split_bf16(v.z, h2, l2); split_bf16(v.w, h3, l3);
    __nv_bfloat162* h2p = reinterpret_cast<__nv_bfloat162*>(h);
    __nv_bfloat162* l2p = reinterpret_cast<__nv_bfloat162*>(l);
    h2p[i*2]   = __nv_bfloat162(h0, h1);
    h2p[i*2+1] = __nv_bfloat162(h2, h3);
    l2p[i*2]   = __nv_bfloat162(l0, l1);
    l2p[i*2+1] = __nv_bfloat162(l2, l3);
}

__global__ void cvt_dtr(const float* __restrict__ xdbl, bf16* __restrict__ h,
                        bf16* __restrict__ l) {
    int i = blockIdx.x * blockDim.x + threadIdx.x;
    if (i >= MROWS * DTRANK / 4) return;
    int row = i >> 4, c4 = (i & 15) * 4;
    float4 v = *reinterpret_cast<const float4*>(&xdbl[(size_t)row * XPROJ_N + c4]);
    bf16 h0, h1, h2, h3, l0, l1, l2, l3;
    split_bf16(v.x, h0, l0); split_bf16(v.y, h1, l1);
    split_bf16(v.z, h2, l2); split_bf16(v.w, h3, l3);
    __nv_bfloat162* h2p = reinterpret_cast<__nv_bfloat162*>(h + (size_t)row * DTRANK + c4);
    __nv_bfloat162* l2p = reinterpret_cast<__nv_bfloat162*>(l + (size_t)row * DTRANK + c4);
    h2p[0] = __nv_bfloat162(h0, h1); h2p[1] = __nv_bfloat162(h2, h3);
    l2p[0] = __nv_bfloat162(l0, l1); l2p[1] = __nv_bfloat162(l2, l3);
}

// ---------------- LayerNorm (fused hi/lo split output) ----------------------
__global__ void ln_kernel(const float* __restrict__ x,
                          const float* __restrict__ w,
                          const float* __restrict__ b,
                          bf16* __restrict__ xnh, bf16* __restrict__ xnl) {
    int row = blockIdx.x;
    int tid = threadIdx.x;
    const float4* xr = reinterpret_cast<const float4*>(x + row * DIM);
    float4 v = xr[tid];
    float s  = v.x + v.y + v.z + v.w;
    float sq = v.x*v.x + v.y*v.y + v.z*v.z + v.w*v.w;
    __shared__ float red[2][8];
    for (int off = 16; off > 0; off >>= 1) {
        s  += __shfl_xor_sync(0xffffffffu, s,  off);
        sq += __shfl_xor_sync(0xffffffffu, sq, off);
    }
    int warp = tid >> 5, lane = tid & 31;
    if (lane == 0) { red[0][warp] = s; red[1][warp] = sq; }
    __syncthreads();
    if (warp == 0) {
        float a = (lane < 8) ? red[0][lane] : 0.f;
        float c = (lane < 8) ? red[1][lane] : 0.f;
        for (int off = 4; off > 0; off >>= 1) {
            a += __shfl_xor_sync(0xffffffffu, a, off);
            c += __shfl_xor_sync(0xffffffffu, c, off);
        }
        if (lane == 0) { red[0][0] = a; red[1][0] = c; }
    }
    __syncthreads();
    float mu  = red[0][0] * (1.f / DIM);
    float var = red[1][0] * (1.f / DIM) - mu * mu;
    float rs  = rsqrtf(var + 1e-5f);
    const float4* w4 = reinterpret_cast<const float4*>(w);
    const float4* b4 = reinterpret_cast<const float4*>(b);
    float4 ww = w4[tid], bb = b4[tid];
    float o0 = (v.x - mu) * rs * ww.x + bb.x;
    float o1 = (v.y - mu) * rs * ww.y + bb.y;
    float o2 = (v.z - mu) * rs * ww.z + bb.z;
    float o3 = (v.w - mu) * rs * ww.w + bb.w;
    bf16 h0, h1, h2, h3, l0, l1, l2, l3;
    split_bf16(o0, h0, l0); split_bf16(o1, h1, l1);
    split_bf16(o2, h2, l2); split_bf16(o3, h3, l3);
    __nv_bfloat162* hp = reinterpret_cast<__nv_bfloat162*>(xnh + (size_t)row * DIM + tid * 4);
    __nv_bfloat162* lp = reinterpret_cast<__nv_bfloat162*>(xnl + (size_t)row * DIM + tid * 4);
    hp[0] = __nv_bfloat162(h0, h1); hp[1] = __nv_bfloat162(h2, h3);
    lp[0] = __nv_bfloat162(l0, l1); lp[1] = __nv_bfloat162(l2, l3);
}

// ---------------- xproj split-K: partial + reduce ---------------------------
__global__ void xproj_partial(const float* __restrict__ Au, const float* __restrict__ W,
                              float* __restrict__ part) {
    __shared__ float As[32][33];
    __shared__ float Ws[32][97];
    int tid = threadIdx.x;
    int m0 = blockIdx.x * 32;
    int split = blockIdx.y;
    int kbase = split * (DI / NSPLIT);
    int tx = tid & 15, ty = tid >> 4;
    float acc[2][6];
    #pragma unroll
    for (int i = 0; i < 2; i++)
        #pragma unroll
        for (int j = 0; j < 6; j++) acc[i][j] = 0.f;

    for (int k0 = 0; k0 < DI / NSPLIT; k0 += 32) {
        {
            int row = tid >> 3, j = tid & 7;
            float4 v = *reinterpret_cast<const float4*>(&Au[(size_t)(m0 + row) * DI + kbase + k0 + j * 4]);
            As[j*4+0][row] = v.x; As[j*4+1][row] = v.y;
            As[j*4+2][row] = v.z; As[j*4+3][row] = v.w;
        }
        #pragma unroll
        for (int it = 0; it < 3; it++) {
            int i = tid + it * 256;
            int row = i >> 3, j = i & 7;
            float4 v = *reinterpret_cast<const float4*>(&W[(size_t)row * DI + kbase + k0 + j * 4]);
            Ws[j*4+0][row] = v.x; Ws[j*4+1][row] = v.y;
            Ws[j*4+2][row] = v.z; Ws[j*4+3][row] = v.w;
        }
        __syncthreads();
        #pragma unroll
        for (int kk = 0; kk < 32; kk++) {
            float a0 = As[kk][ty * 2 + 0], a1 = As[kk][ty * 2 + 1];
            float w[6];
            #pragma unroll
            for (int j = 0; j < 6; j++) w[j] = Ws[kk][tx * 6 + j];
            #pragma unroll
            for (int j = 0; j < 6; j++) {
                acc[0][j] = fmaf(a0, w[j], acc[0][j]);
                acc[1][j] = fmaf(a1, w[j], acc[1][j]);
            }
        }
        __syncthreads();
    }
    float* dst = part + (size_t)split * MROWS * XPROJ_N;
    #pragma unroll
    for (int i = 0; i < 2; i++)
        #pragma unroll
        for (int j = 0; j < 6; j++)
            dst[(size_t)(m0 + ty * 2 + i) * XPROJ_N + tx * 6 + j] = acc[i][j];
}

__global__ void xproj_reduce(const float* __restrict__ part, float* __restrict__ xdbl) {
    int i = blockIdx.x * blockDim.x + threadIdx.x;
    const int TOT4 = MROWS * XPROJ_N / 4;
    if (i >= TOT4) return;
    float4 s = reinterpret_cast<const float4*>(part)[i];
    #pragma unroll
    for (int sp = 1; sp < NSPLIT; sp++) {
        float4 v = reinterpret_cast<const float4*>(part + (size_t)sp * MROWS * XPROJ_N)[i];
        s.x += v.x; s.y += v.y; s.z += v.z; s.w += v.w;
    }
    reinterpret_cast<float4*>(xdbl)[i] = s;
}

// ---------------- causal depthwise conv (k=4) + SiLU ------------------------
__global__ void conv_silu_kernel(const float* __restrict__ xz,
                                 const float* __restrict__ cw,
                                 const float* __restrict__ cb,
                                 float* __restrict__ u) {
    int idx = blockIdx.x * blockDim.x + threadIdx.x;
    if (idx >= BB * LL * DI) return;
    int e = idx & (DI - 1);
    int l = (idx >> 11) & (LL - 1);
    int b = idx >> 21;
    float acc = cb[e];
    #pragma unroll
    for (int k = 0; k < 4; k++) {
        int ls = l + k - 3;
        if (ls >= 0)
            acc = fmaf(cw[e * 4 + k], xz[((size_t)(b * LL + ls)) * (2 * DI) + e], acc);
    }
    float s = acc / (1.f + __expf(-acc));
    u[(size_t)(b * LL + l) * DI + e] = s;
}

// ---------------- SSM selective scan (writes y as hi/lo bf16) ---------------
#define CHUNK 64
__global__ void scan_kernel(const float* __restrict__ dt,
                            const float* __restrict__ u,
                            const float* __restrict__ xdbl,
                            const float* __restrict__ xz,
                            const float* __restrict__ a_log,
                            const float* __restrict__ d_skip,
                            bf16* __restrict__ yh, bf16* __restrict__ yl) {
    __shared__ float sB [CHUNK][DSTATE];
    __shared__ float sC [CHUNK][DSTATE];
    __shared__ float sDt[CHUNK][16];
    __shared__ float sU [CHUNK][16];
    __shared__ float sZ [CHUNK][16];
    int tid  = threadIdx.x;
    int g    = tid >> 4;
    int lane = tid & 15;
    int c0   = blockIdx.x * 16;
    int b    = c0 >> 11;
    int e0   = c0 & (DI - 1);
    int e    = e0 + g;
    float A_n = -__expf(a_log[e * DSTATE + lane]);
    float dsk = d_skip[e];
    float h = 0.f;
    int rowbase = b * LL;
    for (int l0 = 0; l0 < LL; l0 += CHUNK) {
        __syncthreads();
        for (int i = tid; i < CHUNK * 2 * DSTATE; i += 256) {
            int r = i >> 5, j = i & 31;
            float v = xdbl[(size_t)(rowbase + l0 + r) * XPROJ_N + DTRANK + j];
            if (j < DSTATE) sB[r][j] = v; else sC[r][j - DSTATE] = v;
        }
        for (int i = tid; i < CHUNK * 16; i += 256) {
            int r = i >> 4, j = i & 15;
            size_t m = (size_t)(rowbase + l0 + r);
            sDt[r][j] = dt[m * DI + e0 + j];
            sU [r][j] = u [m * DI + e0 + j];
            sZ [r][j] = xz[m * (2 * DI) + DI + e0 + j];
        }
        __syncthreads();
        #pragma unroll 4
        for (int r = 0; r < CHUNK; r++) {
            float dtv = sDt[r][g];
            float uv  = sU [r][g];
            float dA  = __expf(dtv * A_n);
            float dBu = dtv * sB[r][lane] * uv;
            h = fmaf(dA, h, dBu);
            float yv = h * sC[r][lane];
            yv += __shfl_xor_sync(0xffffffffu, yv, 8);
            yv += __shfl_xor_sync(0xffffffffu, yv, 4);
            yv += __shfl_xor_sync(0xffffffffu, yv, 2);
            yv += __shfl_xor_sync(0xffffffffu, yv, 1);
            if (lane == 0) {
                float zv = sZ[r][g];
                float sz = zv / (1.f + __expf(-zv));
                float yo = (yv + uv * dsk) * sz;
                bf16 hh, ll;
                split_bf16(yo, hh, ll);
                size_t o = (size_t)(rowbase + l0 + r) * DI + e;
                yh[o] = hh; yl[o] = ll;
            }
        }
    }
}

// ---------------- launch -----------------------------------------------------
extern "C" void kernel_launch(void* const* d_in, const int* in_sizes, int n_in,
                              void* d_out, int out_size) {
    const float* x      = (const float*)d_in[0];
    const float* ln_w   = (const float*)d_in[1];
    const float* ln_b   = (const float*)d_in[2];
    const float* w_in   = (const float*)d_in[3];
    const float* conv_w = (const float*)d_in[4];
    const float* conv_b = (const float*)d_in[5];
    const float* w_xpr  = (const float*)d_in[6];
    const float* w_dt   = (const float*)d_in[7];
    const float* b_dt   = (const float*)d_in[8];
    const float* a_log  = (const float*)d_in[9];
    const float* d_skip = (const float*)d_in[10];
    const float* w_out  = (const float*)d_in[11];
    float* out = (float*)d_out;

    float *xz, *u, *xdbl, *dt, *part;
    bf16 *xnh, *xnl, *winh, *winl, *yh, *yl, *woh, *wol, *dtrh, *dtrl, *wdth, *wdtl;
    cudaGetSymbolAddress((void**)&xz,   g_xz);
    cudaGetSymbolAddress((void**)&u,    g_u);
    cudaGetSymbolAddress((void**)&xdbl, g_xdbl);
    cudaGetSymbolAddress((void**)&dt,   g_dt);
    cudaGetSymbolAddress((void**)&part, g_part);
    cudaGetSymbolAddress((void**)&xnh,  g_xnh);
    cudaGetSymbolAddress((void**)&xnl,  g_xnl);
    cudaGetSymbolAddress((void**)&winh, g_winh);
    cudaGetSymbolAddress((void**)&winl, g_winl);
    cudaGetSymbolAddress((void**)&yh,   g_yh);
    cudaGetSymbolAddress((void**)&yl,   g_yl);
    cudaGetSymbolAddress((void**)&woh,  g_woh);
    cudaGetSymbolAddress((void**)&wol,  g_wol);
    cudaGetSymbolAddress((void**)&dtrh, g_dtrh);
    cudaGetSymbolAddress((void**)&dtrl, g_dtrl);
    cudaGetSymbolAddress((void**)&wdth, g_wdth);
    cudaGetSymbolAddress((void**)&wdtl, g_wdtl);

    const int SMEM_GT = 2 * 32768;   // 64 KB, 2-stage double buffer
    cudaFuncSetAttribute(gemm_bf16x2<0>, cudaFuncAttributeMaxDynamicSharedMemorySize, SMEM_GT);
    cudaFuncSetAttribute(gemm_bf16x2<1>, cudaFuncAttributeMaxDynamicSharedMemorySize, SMEM_GT);
    cudaFuncSetAttribute(gemm_bf16x2<2>, cudaFuncAttributeMaxDynamicSharedMemorySize, SMEM_GT);

    // 1. w_in conversion
    cvt_hilo<<<(2*DI*DIM/4 + 255)/256, 256>>>(w_in,  winh, winl, 2*DI*DIM/4);
    // 2. LayerNorm (+ hi/lo split)
    ln_kernel<<<MROWS, 256>>>(x, ln_w, ln_b, xnh, xnl);
    // 3. w_out conversion
    cvt_hilo<<<(DIM*DI/4 + 255)/256, 256>>>(w_out, woh,  wol,  DIM*DI/4);
    // 4. xz = xn @ w_in^T   (2048 x 4096 x 1024)  [bf16x2 mma]
    gemm_bf16x2<0><<<dim3(4096/128, MROWS/128), 256, SMEM_GT>>>(
        xnh, xnl, winh, winl, xz, nullptr, DIM, 2*DI);
    // 5. u = silu(conv(xs))
    conv_silu_kernel<<<(BB*LL*DI)/256, 256>>>(xz, conv_w, conv_b, u);
    // 6. w_dt conversion
    cvt_hilo<<<(DI*DTRANK/4 + 255)/256, 256>>>(w_dt, wdth, wdtl, DI*DTRANK/4);
    // 7-8. x_dbl = u @ w_xproj^T  (2048 x 96 x 2048)  [split-K fp32]
    xproj_partial<<<dim3(MROWS/32, NSPLIT), 256>>>(u, w_xpr, part);
    xproj_reduce<<<(MROWS*XPROJ_N/4 + 255)/256, 256>>>(part, xdbl);
    // 9. dt_r hi/lo extract
    cvt_dtr<<<(MROWS*DTRANK/4 + 255)/256, 256>>>(xdbl, dtrh, dtrl);
    // 10. dt = softplus(dt_r @ w_dt^T + b_dt)  (2048 x 2048 x 64)  [bf16x2 mma]
    gemm_bf16x2<1><<<dim3(DI/128, MROWS/128), 256, SMEM_GT>>>(
        dtrh, dtrl, wdth, wdtl, dt, b_dt, DTRANK, DI);
    // 11. selective scan (+ skip + gate, hi/lo split output)
    scan_kernel<<<(BB*DI)/16, 256>>>(dt, u, xdbl, xz, a_log, d_skip, yh, yl);
    // 12. out = residual + y @ w_out^T  (2048 x 1024 x 2048)  [bf16x2 mma]
    gemm_bf16x2<2><<<dim3(DIM/128, MROWS/128), 256, SMEM_GT>>>(
        yh, yl, woh, wol, out, x, DI, DIM);
}

// round 6
// speedup vs baseline: 1.6036x; 1.0055x over previous
#include <cuda_runtime.h>
#include <cuda_bf16.h>
#include <math.h>
#include <stdint.h>

// Problem shapes (fixed by the reference)
#define BB      2
#define LL      1024
#define DIM     1024
#define DI      2048          // d_inner
#define MROWS   (BB*LL)       // 2048
#define DTRANK  64
#define DSTATE  16
#define XPROJ_N (DTRANK + 2*DSTATE)  // 96
#define NSPLIT  8

typedef __nv_bfloat16 bf16;

// ---------------- scratch (device globals; no allocation allowed) ----------
__device__ float g_xz  [MROWS * 2 * DI];
__device__ float g_u   [MROWS * DI];
__device__ float g_xdbl[MROWS * XPROJ_N];
__device__ float g_dt  [MROWS * DI];
__device__ float g_part[NSPLIT * MROWS * XPROJ_N];

__device__ bf16 g_xnh [MROWS * DIM],   g_xnl [MROWS * DIM];
__device__ bf16 g_winh[2*DI * DIM],    g_winl[2*DI * DIM];
__device__ bf16 g_yh  [MROWS * DI],    g_yl  [MROWS * DI];
__device__ bf16 g_woh [DIM * DI],      g_wol [DIM * DI];
__device__ bf16 g_dtrh[MROWS * DTRANK],g_dtrl[MROWS * DTRANK];
__device__ bf16 g_wdth[DI * DTRANK],   g_wdtl[DI * DTRANK];

// =================== baseline PTX helpers (no arch-'a' features) ============
__device__ __forceinline__ uint32_t smem_u32(const void* p) {
    uint32_t a;
    asm("{ .reg .u64 t; cvta.to.shared.u64 t, %1; cvt.u32.u64 %0, t; }" : "=r"(a) : "l"(p));
    return a;
}
#define CP_ASYNC16(dst, src) \
    asm volatile("cp.async.cg.shared.global [%0], [%1], 16;" :: "r"(dst), "l"(src))
#define CP_COMMIT() asm volatile("cp.async.commit_group;" ::: "memory")
#define CP_WAIT(n)  asm volatile("cp.async.wait_group %0;" :: "n"(n) : "memory")

__device__ __forceinline__ void ldsm4(uint32_t* r, uint32_t addr) {
    asm volatile("ldmatrix.sync.aligned.m8n8.x4.shared.b16 {%0,%1,%2,%3}, [%4];"
                 : "=r"(r[0]), "=r"(r[1]), "=r"(r[2]), "=r"(r[3]) : "r"(addr));
}
__device__ __forceinline__ void mma_bf16(float* c, const uint32_t* a, const uint32_t* b) {
    asm volatile("mma.sync.aligned.m16n8k16.row.col.f32.bf16.bf16.f32 "
                 "{%0,%1,%2,%3}, {%4,%5,%6,%7}, {%8,%9}, {%0,%1,%2,%3};"
                 : "+f"(c[0]), "+f"(c[1]), "+f"(c[2]), "+f"(c[3])
                 : "r"(a[0]), "r"(a[1]), "r"(a[2]), "r"(a[3]), "r"(b[0]), "r"(b[1]));
}
// SW64 swizzle for 64-byte stage rows (verified conflict-free for ldsm phases)
__device__ __forceinline__ uint32_t sw64(uint32_t off) { return off ^ ((off >> 3) & 0x30); }

__device__ __forceinline__ void split_bf16(float x, bf16& h, bf16& l) {
    h = __float2bfloat16(x);
    l = __float2bfloat16(x - __bfloat162float(h));
}

// =================== bf16x2 mma.sync GEMM: C = A @ B^T ======================
// BM=128, BN in {128,64}, BK=32/stage, 3-stage cp.async ring, 8 warps,
// 2 CTAs/SM. EPI: 0 none, 1 softplus+bias, 2 +resid
template<int EPI, int BN>
__global__ void __launch_bounds__(256, 2)
gemm_bf16x2(const bf16* __restrict__ Ah, const bf16* __restrict__ Al,
            const bf16* __restrict__ Bh, const bf16* __restrict__ Bl,
            float* __restrict__ C, const float* __restrict__ aux,
            int K, int ldc) {
    extern __shared__ char smem[];
    const uint32_t sb = smem_u32(smem);
    constexpr int ABY = 128 * 64;            // bytes per A matrix per stage
    constexpr int BBY = BN * 64;             // bytes per B matrix per stage
    constexpr int STG = 2 * ABY + 2 * BBY;   // stage size
    constexpr int MT  = (BN == 128) ? 4 : 2; // m16 tiles per warp
    const int tid = threadIdx.x, wid = tid >> 5, lane = tid & 31;
    const int m0 = blockIdx.y * 128, n0 = blockIdx.x * BN;
    const int wm = (BN == 128) ? (wid >> 2) : (wid >> 1);
    const int wn = (BN == 128) ? (wid & 3)  : (wid & 1);

    float acc[MT][4][4];
    #pragma unroll
    for (int a = 0; a < MT; a++)
        #pragma unroll
        for (int b = 0; b < 4; b++)
            #pragma unroll
            for (int c = 0; c < 4; c++) acc[a][b][c] = 0.f;

    // stage s: [Ah | Al | Bh | Bl], 64B SW64 rows of 32 bf16
    auto load_stage = [&](int s, int kc) {
        uint32_t base = sb + s * STG;
        #pragma unroll
        for (int it = 0; it < 2; it++) {          // A: 2 mats x 128 rows
            int i = tid + it * 256;
            int row = i >> 2, j = i & 3;
            uint32_t so = sw64(row * 64 + j * 16);
            CP_ASYNC16(base + so,
                       Ah + (size_t)(m0 + row) * K + kc * 32 + j * 8);
            CP_ASYNC16(base + ABY + so,
                       Al + (size_t)(m0 + row) * K + kc * 32 + j * 8);
        }
        #pragma unroll
        for (int it = 0; it < BN * 4 / 256; it++) {   // B: 2 mats x BN rows
            int i = tid + it * 256;
            int row = i >> 2, j = i & 3;
            uint32_t so = sw64(row * 64 + j * 16);
            CP_ASYNC16(base + 2 * ABY + so,
                       Bh + (size_t)(n0 + row) * K + kc * 32 + j * 8);
            CP_ASYNC16(base + 2 * ABY + BBY + so,
                       Bl + (size_t)(n0 + row) * K + kc * 32 + j * 8);
        }
        CP_COMMIT();
    };

    auto compute = [&](int s) {
        uint32_t pAh = sb + s * STG, pAl = pAh + ABY;
        uint32_t pBh = pAl + ABY,    pBl = pBh + BBY;
        #pragma unroll
        for (int kk = 0; kk < 2; kk++) {
            uint32_t bh[2][4], bl[2][4];
            int grp = lane >> 3, l8 = lane & 7;
            int kbB = kk * 32 + ((grp & 1) << 4);
            #pragma unroll
            for (int pr = 0; pr < 2; pr++) {
                int row = wn * 32 + pr * 16 + ((grp >> 1) << 3) + l8;
                uint32_t off = sw64(row * 64 + kbB);
                ldsm4(bh[pr], pBh + off);
                ldsm4(bl[pr], pBl + off);
            }
            int kbA = kk * 32 + ((lane >> 4) << 4);
            #pragma unroll
            for (int mt = 0; mt < MT; mt++) {
                uint32_t ah[4], al[4];
                int row = wm * (MT * 16) + mt * 16 + (lane & 15);
                uint32_t off = sw64(row * 64 + kbA);
                ldsm4(ah, pAh + off);
                ldsm4(al, pAl + off);
                #pragma unroll
                for (int pr = 0; pr < 2; pr++)
                    #pragma unroll
                    for (int half = 0; half < 2; half++) {
                        int nt = pr * 2 + half;
                        mma_bf16(acc[mt][nt], ah, &bh[pr][half * 2]);
                        mma_bf16(acc[mt][nt], ah, &bl[pr][half * 2]);
                        mma_bf16(acc[mt][nt], al, &bh[pr][half * 2]);
                    }
            }
        }
    };

    const int nst = K >> 5;
    load_stage(0, 0);
    if (nst > 1) load_stage(1, 1);
    int slot = 0;
    for (int kc = 0; kc < nst; kc++) {
        if (kc + 1 < nst) CP_WAIT(1); else CP_WAIT(0);
        __syncthreads();                       // stage kc ready, prev compute done
        if (kc + 2 < nst) load_stage((kc + 2) % 3, kc + 2);
        compute(slot);
        slot = (slot + 1 == 3) ? 0 : slot + 1;
    }

    // epilogue: write fp32 directly from fragments
    #pragma unroll
    for (int mt = 0; mt < MT; mt++) {
        #pragma unroll
        for (int nt = 0; nt < 4; nt++) {
            int row = m0 + wm * (MT * 16) + mt * 16 + (lane >> 2);
            int col = n0 + wn * 32 + nt * 8 + (lane & 3) * 2;
            float v[4] = {acc[mt][nt][0], acc[mt][nt][1], acc[mt][nt][2], acc[mt][nt][3]};
            if (EPI == 1) {
                #pragma unroll
                for (int i = 0; i < 4; i++) {
                    float t = v[i] + aux[col + (i & 1)];
                    v[i] = fmaxf(t, 0.f) + log1pf(__expf(-fabsf(t)));
                }
            } else if (EPI == 2) {
                v[0] += aux[(size_t)row * ldc + col];
                v[1] += aux[(size_t)row * ldc + col + 1];
                v[2] += aux[(size_t)(row + 8) * ldc + col];
                v[3] += aux[(size_t)(row + 8) * ldc + col + 1];
            }
            *reinterpret_cast<float2*>(&C[(size_t)row * ldc + col])       = make_float2(v[0], v[1]);
            *reinterpret_cast<float2*>(&C[(size_t)(row + 8) * ldc + col]) = make_float2(v[2], v[3]);
        }
    }
}

// ---------------- conversion kernels ---------------------------------------
__global__ void cvt_hilo(const float* __restrict__ s, bf16* __restrict__ h,
                         bf16* __restrict__ l, int n4) {
    int i = blockIdx.x * blockDim.x + threadIdx.x;
    if (i >= n4) return;
    float4 v = reinterpret_cast<const float4*>(s)[i];
    bf16 h0, h1, h2, h3, l0, l1, l2, l3;
    split_bf16(v.x, h0, l0); split_bf16(v.y, h1, l1);
    split_bf16(v.z, h2, l2); split_bf16(v.w, h3, l3);
    __nv_bfloat162* h2p = reinterpret_cast<__nv_bfloat162*>(h);
    __nv_bfloat162* l2p = reinterpret_cast<__nv_bfloat162*>(l);
    h2p[i*2]   = __nv_bfloat162(h0, h1);
    h2p[i*2+1] = __nv_bfloat162(h2, h3);
    l2p[i*2]   = __nv_bfloat162(l0, l1);
    l2p[i*2+1] = __nv_bfloat162(l2, l3);
}

__global__ void cvt_dtr(const float* __restrict__ xdbl, bf16* __restrict__ h,
                        bf16* __restrict__ l) {
    int i = blockIdx.x * blockDim.x + threadIdx.x;
    if (i >= MROWS * DTRANK / 4) return;
    int row = i >> 4, c4 = (i & 15) * 4;
    float4 v = *reinterpret_cast<const float4*>(&xdbl[(size_t)row * XPROJ_N + c4]);
    bf16 h0, h1, h2, h3, l0, l1, l2, l3;
    split_bf16(v.x, h0, l0); split_bf16(v.y, h1, l1);
    split_bf16(v.z, h2, l2); split_bf16(v.w, h3, l3);
    __nv_bfloat162* h2p = reinterpret_cast<__nv_bfloat162*>(h + (size_t)row * DTRANK + c4);
    __nv_bfloat162* l2p = reinterpret_cast<__nv_bfloat162*>(l + (size_t)row * DTRANK + c4);
    h2p[0] = __nv_bfloat162(h0, h1); h2p[1] = __nv_bfloat162(h2, h3);
    l2p[0] = __nv_bfloat162(l0, l1); l2p[1] = __nv_bfloat162(l2, l3);
}

// ---------------- LayerNorm (fused hi/lo split output) ----------------------
__global__ void ln_kernel(const float* __restrict__ x,
                          const float* __restrict__ w,
                          const float* __restrict__ b,
                          bf16* __restrict__ xnh, bf16* __restrict__ xnl) {
    int row = blockIdx.x;
    int tid = threadIdx.x;
    const float4* xr = reinterpret_cast<const float4*>(x + row * DIM);
    float4 v = xr[tid];
    float s  = v.x + v.y + v.z + v.w;
    float sq = v.x*v.x + v.y*v.y + v.z*v.z + v.w*v.w;
    __shared__ float red[2][8];
    for (int off = 16; off > 0; off >>= 1) {
        s  += __shfl_xor_sync(0xffffffffu, s,  off);
        sq += __shfl_xor_sync(0xffffffffu, sq, off);
    }
    int warp = tid >> 5, lane = tid & 31;
    if (lane == 0) { red[0][warp] = s; red[1][warp] = sq; }
    __syncthreads();
    if (warp == 0) {
        float a = (lane < 8) ? red[0][lane] : 0.f;
        float c = (lane < 8) ? red[1][lane] : 0.f;
        for (int off = 4; off > 0; off >>= 1) {
            a += __shfl_xor_sync(0xffffffffu, a, off);
            c += __shfl_xor_sync(0xffffffffu, c, off);
        }
        if (lane == 0) { red[0][0] = a; red[1][0] = c; }
    }
    __syncthreads();
    float mu  = red[0][0] * (1.f / DIM);
    float var = red[1][0] * (1.f / DIM) - mu * mu;
    float rs  = rsqrtf(var + 1e-5f);
    const float4* w4 = reinterpret_cast<const float4*>(w);
    const float4* b4 = reinterpret_cast<const float4*>(b);
    float4 ww = w4[tid], bb = b4[tid];
    float o0 = (v.x - mu) * rs * ww.x + bb.x;
    float o1 = (v.y - mu) * rs * ww.y + bb.y;
    float o2 = (v.z - mu) * rs * ww.z + bb.z;
    float o3 = (v.w - mu) * rs * ww.w + bb.w;
    bf16 h0, h1, h2, h3, l0, l1, l2, l3;
    split_bf16(o0, h0, l0); split_bf16(o1, h1, l1);
    split_bf16(o2, h2, l2); split_bf16(o3, h3, l3);
    __nv_bfloat162* hp = reinterpret_cast<__nv_bfloat162*>(xnh + (size_t)row * DIM + tid * 4);
    __nv_bfloat162* lp = reinterpret_cast<__nv_bfloat162*>(xnl + (size_t)row * DIM + tid * 4);
    hp[0] = __nv_bfloat162(h0, h1); hp[1] = __nv_bfloat162(h2, h3);
    lp[0] = __nv_bfloat162(l0, l1); lp[1] = __nv_bfloat162(l2, l3);
}

// ---------------- xproj split-K: partial + reduce ---------------------------
__global__ void xproj_partial(const float* __restrict__ Au, const float* __restrict__ W,
                              float* __restrict__ part) {
    __shared__ float As[32][33];
    __shared__ float Ws[32][97];
    int tid = threadIdx.x;
    int m0 = blockIdx.x * 32;
    int split = blockIdx.y;
    int kbase = split * (DI / NSPLIT);
    int tx = tid & 15, ty = tid >> 4;
    float acc[2][6];
    #pragma unroll
    for (int i = 0; i < 2; i++)
        #pragma unroll
        for (int j = 0; j < 6; j++) acc[i][j] = 0.f;

    for (int k0 = 0; k0 < DI / NSPLIT; k0 += 32) {
        {
            int row = tid >> 3, j = tid & 7;
            float4 v = *reinterpret_cast<const float4*>(&Au[(size_t)(m0 + row) * DI + kbase + k0 + j * 4]);
            As[j*4+0][row] = v.x; As[j*4+1][row] = v.y;
            As[j*4+2][row] = v.z; As[j*4+3][row] = v.w;
        }
        #pragma unroll
        for (int it = 0; it < 3; it++) {
            int i = tid + it * 256;
            int row = i >> 3, j = i & 7;
            float4 v = *reinterpret_cast<const float4*>(&W[(size_t)row * DI + kbase + k0 + j * 4]);
            Ws[j*4+0][row] = v.x; Ws[j*4+1][row] = v.y;
            Ws[j*4+2][row] = v.z; Ws[j*4+3][row] = v.w;
        }
        __syncthreads();
        #pragma unroll
        for (int kk = 0; kk < 32; kk++) {
            float a0 = As[kk][ty * 2 + 0], a1 = As[kk][ty * 2 + 1];
            float w[6];
            #pragma unroll
            for (int j = 0; j < 6; j++) w[j] = Ws[kk][tx * 6 + j];
            #pragma unroll
            for (int j = 0; j < 6; j++) {
                acc[0][j] = fmaf(a0, w[j], acc[0][j]);
                acc[1][j] = fmaf(a1, w[j], acc[1][j]);
            }
        }
        __syncthreads();
    }
    float* dst = part + (size_t)split * MROWS * XPROJ_N;
    #pragma unroll
    for (int i = 0; i < 2; i++)
        #pragma unroll
        for (int j = 0; j < 6; j++)
            dst[(size_t)(m0 + ty * 2 + i) * XPROJ_N + tx * 6 + j] = acc[i][j];
}

__global__ void xproj_reduce(const float* __restrict__ part, float* __restrict__ xdbl) {
    int i = blockIdx.x * blockDim.x + threadIdx.x;
    const int TOT4 = MROWS * XPROJ_N / 4;
    if (i >= TOT4) return;
    float4 s = reinterpret_cast<const float4*>(part)[i];
    #pragma unroll
    for (int sp = 1; sp < NSPLIT; sp++) {
        float4 v = reinterpret_cast<const float4*>(part + (size_t)sp * MROWS * XPROJ_N)[i];
        s.x += v.x; s.y += v.y; s.z += v.z; s.w += v.w;
    }
    reinterpret_cast<float4*>(xdbl)[i] = s;
}

// ---------------- causal depthwise conv (k=4) + SiLU ------------------------
__global__ void conv_silu_kernel(const float* __restrict__ xz,
                                 const float* __restrict__ cw,
                                 const float* __restrict__ cb,
                                 float* __restrict__ u) {
    int idx = blockIdx.x * blockDim.x + threadIdx.x;
    if (idx >= BB * LL * DI) return;
    int e = idx & (DI - 1);
    int l = (idx >> 11) & (LL - 1);
    int b = idx >> 21;
    float acc = cb[e];
    #pragma unroll
    for (int k = 0; k < 4; k++) {
        int ls = l + k - 3;
        if (ls >= 0)
            acc = fmaf(cw[e * 4 + k], xz[((size_t)(b * LL + ls)) * (2 * DI) + e], acc);
    }
    float s = acc / (1.f + __expf(-acc));
    u[(size_t)(b * LL + l) * DI + e] = s;
}

// ---------------- SSM selective scan (writes y as hi/lo bf16) ---------------
#define CHUNK 64
__global__ void scan_kernel(const float* __restrict__ dt,
                            const float* __restrict__ u,
                            const float* __restrict__ xdbl,
                            const float* __restrict__ xz,
                            const float* __restrict__ a_log,
                            const float* __restrict__ d_skip,
                            bf16* __restrict__ yh, bf16* __restrict__ yl) {
    __shared__ float sB [CHUNK][DSTATE];
    __shared__ float sC [CHUNK][DSTATE];
    __shared__ float sDt[CHUNK][16];
    __shared__ float sU [CHUNK][16];
    __shared__ float sZ [CHUNK][16];
    int tid  = threadIdx.x;
    int g    = tid >> 4;
    int lane = tid & 15;
    int c0   = blockIdx.x * 16;
    int b    = c0 >> 11;
    int e0   = c0 & (DI - 1);
    int e    = e0 + g;
    float A_n = -__expf(a_log[e * DSTATE + lane]);
    float dsk = d_skip[e];
    float h = 0.f;
    int rowbase = b * LL;
    for (int l0 = 0; l0 < LL; l0 += CHUNK) {
        __syncthreads();
        for (int i = tid; i < CHUNK * 2 * DSTATE; i += 256) {
            int r = i >> 5, j = i & 31;
            float v = xdbl[(size_t)(rowbase + l0 + r) * XPROJ_N + DTRANK + j];
            if (j < DSTATE) sB[r][j] = v; else sC[r][j - DSTATE] = v;
        }
        for (int i = tid; i < CHUNK * 16; i += 256) {
            int r = i >> 4, j = i & 15;
            size_t m = (size_t)(rowbase + l0 + r);
            sDt[r][j] = dt[m * DI + e0 + j];
            sU [r][j] = u [m * DI + e0 + j];
            sZ [r][j] = xz[m * (2 * DI) + DI + e0 + j];
        }
        __syncthreads();
        #pragma unroll 4
        for (int r = 0; r < CHUNK; r++) {
            float dtv = sDt[r][g];
            float uv  = sU [r][g];
            float dA  = __expf(dtv * A_n);
            float dBu = dtv * sB[r][lane] * uv;
            h = fmaf(dA, h, dBu);
            float yv = h * sC[r][lane];
            yv += __shfl_xor_sync(0xffffffffu, yv, 8);
            yv += __shfl_xor_sync(0xffffffffu, yv, 4);
            yv += __shfl_xor_sync(0xffffffffu, yv, 2);
            yv += __shfl_xor_sync(0xffffffffu, yv, 1);
            if (lane == 0) {
                float zv = sZ[r][g];
                float sz = zv / (1.f + __expf(-zv));
                float yo = (yv + uv * dsk) * sz;
                bf16 hh, ll;
                split_bf16(yo, hh, ll);
                size_t o = (size_t)(rowbase + l0 + r) * DI + e;
                yh[o] = hh; yl[o] = ll;
            }
        }
    }
}

// ---------------- launch -----------------------------------------------------
extern "C" void kernel_launch(void* const* d_in, const int* in_sizes, int n_in,
                              void* d_out, int out_size) {
    const float* x      = (const float*)d_in[0];
    const float* ln_w   = (const float*)d_in[1];
    const float* ln_b   = (const float*)d_in[2];
    const float* w_in   = (const float*)d_in[3];
    const float* conv_w = (const float*)d_in[4];
    const float* conv_b = (const float*)d_in[5];
    const float* w_xpr  = (const float*)d_in[6];
    const float* w_dt   = (const float*)d_in[7];
    const float* b_dt   = (const float*)d_in[8];
    const float* a_log  = (const float*)d_in[9];
    const float* d_skip = (const float*)d_in[10];
    const float* w_out  = (const float*)d_in[11];
    float* out = (float*)d_out;

    float *xz, *u, *xdbl, *dt, *part;
    bf16 *xnh, *xnl, *winh, *winl, *yh, *yl, *woh, *wol, *dtrh, *dtrl, *wdth, *wdtl;
    cudaGetSymbolAddress((void**)&xz,   g_xz);
    cudaGetSymbolAddress((void**)&u,    g_u);
    cudaGetSymbolAddress((void**)&xdbl, g_xdbl);
    cudaGetSymbolAddress((void**)&dt,   g_dt);
    cudaGetSymbolAddress((void**)&part, g_part);
    cudaGetSymbolAddress((void**)&xnh,  g_xnh);
    cudaGetSymbolAddress((void**)&xnl,  g_xnl);
    cudaGetSymbolAddress((void**)&winh, g_winh);
    cudaGetSymbolAddress((void**)&winl, g_winl);
    cudaGetSymbolAddress((void**)&yh,   g_yh);
    cudaGetSymbolAddress((void**)&yl,   g_yl);
    cudaGetSymbolAddress((void**)&woh,  g_woh);
    cudaGetSymbolAddress((void**)&wol,  g_wol);
    cudaGetSymbolAddress((void**)&dtrh, g_dtrh);
    cudaGetSymbolAddress((void**)&dtrl, g_dtrl);
    cudaGetSymbolAddress((void**)&wdth, g_wdth);
    cudaGetSymbolAddress((void**)&wdtl, g_wdtl);

    const int SMEM128 = 3 * 32768;   // BN=128: 96 KB, 3-stage ring
    const int SMEM64  = 3 * 24576;   // BN=64:  72 KB, 3-stage ring
    cudaFuncSetAttribute((const void*)gemm_bf16x2<0,128>, cudaFuncAttributeMaxDynamicSharedMemorySize, SMEM128);
    cudaFuncSetAttribute((const void*)gemm_bf16x2<1,128>, cudaFuncAttributeMaxDynamicSharedMemorySize, SMEM128);
    cudaFuncSetAttribute((const void*)gemm_bf16x2<2,64>,  cudaFuncAttributeMaxDynamicSharedMemorySize, SMEM64);

    // 1. w_in conversion
    cvt_hilo<<<(2*DI*DIM/4 + 255)/256, 256>>>(w_in,  winh, winl, 2*DI*DIM/4);
    // 2. LayerNorm (+ hi/lo split)
    ln_kernel<<<MROWS, 256>>>(x, ln_w, ln_b, xnh, xnl);
    // 3. w_out conversion
    cvt_hilo<<<(DIM*DI/4 + 255)/256, 256>>>(w_out, woh,  wol,  DIM*DI/4);
    // 4. xz = xn @ w_in^T   (2048 x 4096 x 1024)  [bf16x2 mma, BN=128]
    gemm_bf16x2<0,128><<<dim3(4096/128, MROWS/128), 256, SMEM128>>>(
        xnh, xnl, winh, winl, xz, nullptr, DIM, 2*DI);
    // 5. u = silu(conv(xs))
    conv_silu_kernel<<<(BB*LL*DI)/256, 256>>>(xz, conv_w, conv_b, u);
    // 6. w_dt conversion
    cvt_hilo<<<(DI*DTRANK/4 + 255)/256, 256>>>(w_dt, wdth, wdtl, DI*DTRANK/4);
    // 7-8. x_dbl = u @ w_xproj^T  (2048 x 96 x 2048)  [split-K fp32]
    xproj_partial<<<dim3(MROWS/32, NSPLIT), 256>>>(u, w_xpr, part);
    xproj_reduce<<<(MROWS*XPROJ_N/4 + 255)/256, 256>>>(part, xdbl);
    // 9. dt_r hi/lo extract
    cvt_dtr<<<(MROWS*DTRANK/4 + 255)/256, 256>>>(xdbl, dtrh, dtrl);
    // 10. dt = softplus(dt_r @ w_dt^T + b_dt)  (2048 x 2048 x 64)  [BN=128]
    gemm_bf16x2<1,128><<<dim3(DI/128, MROWS/128), 256, SMEM128>>>(
        dtrh, dtrl, wdth, wdtl, dt, b_dt, DTRANK, DI);
    // 11. selective scan (+ skip + gate, hi/lo split output)
    scan_kernel<<<(BB*DI)/16, 256>>>(dt, u, xdbl, xz, a_log, d_skip, yh, yl);
    // 12. out = residual + y @ w_out^T  (2048 x 1024 x 2048)  [BN=64, 256 CTAs]
    gemm_bf16x2<2,64><<<dim3(DIM/64, MROWS/128), 256, SMEM64>>>(
        yh, yl, woh, wol, out, x, DI, DIM);
}

// round 7
// speedup vs baseline: 1.8182x; 1.1338x over previous
#include <cuda_runtime.h>
#include <cuda_fp16.h>
#include <math.h>
#include <stdint.h>

// Problem shapes (fixed by the reference)
#define BB      2
#define LL      1024
#define DIM     1024
#define DI      2048          // d_inner
#define MROWS   (BB*LL)       // 2048
#define DTRANK  64
#define DSTATE  16
#define XPROJ_N (DTRANK + 2*DSTATE)  // 96
#define NSPLIT  8

typedef __half fp16;

// ---------------- scratch (device globals; no allocation allowed) ----------
__device__ float g_xz  [MROWS * 2 * DI];
__device__ float g_u   [MROWS * DI];
__device__ float g_xdbl[MROWS * XPROJ_N];
__device__ float g_dt  [MROWS * DI];
__device__ float g_part[NSPLIT * MROWS * XPROJ_N];

__device__ fp16 g_xnh [MROWS * DIM],   g_xnl [MROWS * DIM];
__device__ fp16 g_winh[2*DI * DIM];
__device__ fp16 g_yh  [MROWS * DI],    g_yl  [MROWS * DI];
__device__ fp16 g_woh [DIM * DI];
__device__ fp16 g_dtrh[MROWS * DTRANK],g_dtrl[MROWS * DTRANK];
__device__ fp16 g_wdth[DI * DTRANK];

// =================== baseline PTX helpers (no arch-'a' features) ============
__device__ __forceinline__ uint32_t smem_u32(const void* p) {
    uint32_t a;
    asm("{ .reg .u64 t; cvta.to.shared.u64 t, %1; cvt.u32.u64 %0, t; }" : "=r"(a) : "l"(p));
    return a;
}
#define CP_ASYNC16(dst, src) \
    asm volatile("cp.async.cg.shared.global [%0], [%1], 16;" :: "r"(dst), "l"(src))
#define CP_COMMIT() asm volatile("cp.async.commit_group;" ::: "memory")
#define CP_WAIT(n)  asm volatile("cp.async.wait_group %0;" :: "n"(n) : "memory")

__device__ __forceinline__ void ldsm4(uint32_t* r, uint32_t addr) {
    asm volatile("ldmatrix.sync.aligned.m8n8.x4.shared.b16 {%0,%1,%2,%3}, [%4];"
                 : "=r"(r[0]), "=r"(r[1]), "=r"(r[2]), "=r"(r[3]) : "r"(addr));
}
__device__ __forceinline__ void mma_fp16(float* c, const uint32_t* a, const uint32_t* b) {
    asm volatile("mma.sync.aligned.m16n8k16.row.col.f32.f16.f16.f32 "
                 "{%0,%1,%2,%3}, {%4,%5,%6,%7}, {%8,%9}, {%0,%1,%2,%3};"
                 : "+f"(c[0]), "+f"(c[1]), "+f"(c[2]), "+f"(c[3])
                 : "r"(a[0]), "r"(a[1]), "r"(a[2]), "r"(a[3]), "r"(b[0]), "r"(b[1]));
}
// SW64 swizzle for 64-byte stage rows (verified conflict-free for ldsm phases)
__device__ __forceinline__ uint32_t sw64(uint32_t off) { return off ^ ((off >> 3) & 0x30); }

__device__ __forceinline__ void split_fp16(float x, fp16& h, fp16& l) {
    h = __float2half_rn(x);
    l = __float2half_rn(x - __half2float(h));
}

// =================== fp16 A-split mma.sync GEMM: C = A @ B^T ================
// A in fp16 hi/lo (2 MMAs: Ah*Bh + Al*Bh), B single fp16.
// BM=128, BN in {128,64}, BK=32/stage, 3-stage cp.async ring, 8 warps,
// 2 CTAs/SM. EPI: 0 none, 1 softplus+bias, 2 +resid
template<int EPI, int BN>
__global__ void __launch_bounds__(256, 2)
gemm_f16(const fp16* __restrict__ Ah, const fp16* __restrict__ Al,
         const fp16* __restrict__ Bh,
         float* __restrict__ C, const float* __restrict__ aux,
         int K, int ldc) {
    extern __shared__ char smem[];
    const uint32_t sb = smem_u32(smem);
    constexpr int ABY = 128 * 64;            // bytes per A matrix per stage
    constexpr int BBY = BN * 64;             // bytes for B per stage
    constexpr int STG = 2 * ABY + BBY;       // stage size
    constexpr int MT  = (BN == 128) ? 4 : 2; // m16 tiles per warp
    const int tid = threadIdx.x, wid = tid >> 5, lane = tid & 31;
    const int m0 = blockIdx.y * 128, n0 = blockIdx.x * BN;
    const int wm = (BN == 128) ? (wid >> 2) : (wid >> 1);
    const int wn = (BN == 128) ? (wid & 3)  : (wid & 1);

    float acc[MT][4][4];
    #pragma unroll
    for (int a = 0; a < MT; a++)
        #pragma unroll
        for (int b = 0; b < 4; b++)
            #pragma unroll
            for (int c = 0; c < 4; c++) acc[a][b][c] = 0.f;

    // stage s: [Ah | Al | Bh], 64B SW64 rows of 32 fp16
    auto load_stage = [&](int s, int kc) {
        uint32_t base = sb + s * STG;
        #pragma unroll
        for (int it = 0; it < 2; it++) {          // A: 2 mats x 128 rows
            int i = tid + it * 256;
            int row = i >> 2, j = i & 3;
            uint32_t so = sw64(row * 64 + j * 16);
            CP_ASYNC16(base + so,
                       Ah + (size_t)(m0 + row) * K + kc * 32 + j * 8);
            CP_ASYNC16(base + ABY + so,
                       Al + (size_t)(m0 + row) * K + kc * 32 + j * 8);
        }
        #pragma unroll
        for (int it = 0; it < BN / 64; it++) {    // B: 1 mat x BN rows
            int i = tid + it * 256;
            int row = i >> 2, j = i & 3;
            uint32_t so = sw64(row * 64 + j * 16);
            CP_ASYNC16(base + 2 * ABY + so,
                       Bh + (size_t)(n0 + row) * K + kc * 32 + j * 8);
        }
        CP_COMMIT();
    };

    auto compute = [&](int s) {
        uint32_t pAh = sb + s * STG, pAl = pAh + ABY;
        uint32_t pBh = pAl + ABY;
        #pragma unroll
        for (int kk = 0; kk < 2; kk++) {
            uint32_t bh[2][4];
            int grp = lane >> 3, l8 = lane & 7;
            int kbB = kk * 32 + ((grp & 1) << 4);
            #pragma unroll
            for (int pr = 0; pr < 2; pr++) {
                int row = wn * 32 + pr * 16 + ((grp >> 1) << 3) + l8;
                ldsm4(bh[pr], pBh + sw64(row * 64 + kbB));
            }
            int kbA = kk * 32 + ((lane >> 4) << 4);
            #pragma unroll
            for (int mt = 0; mt < MT; mt++) {
                uint32_t ah[4], al[4];
                int row = wm * (MT * 16) + mt * 16 + (lane & 15);
                uint32_t off = sw64(row * 64 + kbA);
                ldsm4(ah, pAh + off);
                ldsm4(al, pAl + off);
                #pragma unroll
                for (int pr = 0; pr < 2; pr++)
                    #pragma unroll
                    for (int half = 0; half < 2; half++) {
                        int nt = pr * 2 + half;
                        mma_fp16(acc[mt][nt], ah, &bh[pr][half * 2]);
                        mma_fp16(acc[mt][nt], al, &bh[pr][half * 2]);
                    }
            }
        }
    };

    const int nst = K >> 5;
    load_stage(0, 0);
    if (nst > 1) load_stage(1, 1);
    int slot = 0;
    for (int kc = 0; kc < nst; kc++) {
        if (kc + 1 < nst) CP_WAIT(1); else CP_WAIT(0);
        __syncthreads();                       // stage kc ready, prev compute done
        if (kc + 2 < nst) load_stage((kc + 2) % 3, kc + 2);
        compute(slot);
        slot = (slot + 1 == 3) ? 0 : slot + 1;
    }

    // epilogue: write fp32 directly from fragments
    #pragma unroll
    for (int mt = 0; mt < MT; mt++) {
        #pragma unroll
        for (int nt = 0; nt < 4; nt++) {
            int row = m0 + wm * (MT * 16) + mt * 16 + (lane >> 2);
            int col = n0 + wn * 32 + nt * 8 + (lane & 3) * 2;
            float v[4] = {acc[mt][nt][0], acc[mt][nt][1], acc[mt][nt][2], acc[mt][nt][3]};
            if (EPI == 1) {
                #pragma unroll
                for (int i = 0; i < 4; i++) {
                    float t = v[i] + aux[col + (i & 1)];
                    v[i] = fmaxf(t, 0.f) + log1pf(__expf(-fabsf(t)));
                }
            } else if (EPI == 2) {
                v[0] += aux[(size_t)row * ldc + col];
                v[1] += aux[(size_t)row * ldc + col + 1];
                v[2] += aux[(size_t)(row + 8) * ldc + col];
                v[3] += aux[(size_t)(row + 8) * ldc + col + 1];
            }
            *reinterpret_cast<float2*>(&C[(size_t)row * ldc + col])       = make_float2(v[0], v[1]);
            *reinterpret_cast<float2*>(&C[(size_t)(row + 8) * ldc + col]) = make_float2(v[2], v[3]);
        }
    }
}

// ---------------- conversion kernels ---------------------------------------
// weights -> single fp16
__global__ void cvt_w16(const float* __restrict__ s, fp16* __restrict__ h, int n4) {
    int i = blockIdx.x * blockDim.x + threadIdx.x;
    if (i >= n4) return;
    float4 v = reinterpret_cast<const float4*>(s)[i];
    __half2* hp = reinterpret_cast<__half2*>(h);
    hp[i*2]   = __floats2half2_rn(v.x, v.y);
    hp[i*2+1] = __floats2half2_rn(v.z, v.w);
}

// ---------------- LayerNorm (fused fp16 hi/lo split output) -----------------
__global__ void ln_kernel(const float* __restrict__ x,
                          const float* __restrict__ w,
                          const float* __restrict__ b,
                          fp16* __restrict__ xnh, fp16* __restrict__ xnl) {
    int row = blockIdx.x;
    int tid = threadIdx.x;
    const float4* xr = reinterpret_cast<const float4*>(x + row * DIM);
    float4 v = xr[tid];
    float s  = v.x + v.y + v.z + v.w;
    float sq = v.x*v.x + v.y*v.y + v.z*v.z + v.w*v.w;
    __shared__ float red[2][8];
    for (int off = 16; off > 0; off >>= 1) {
        s  += __shfl_xor_sync(0xffffffffu, s,  off);
        sq += __shfl_xor_sync(0xffffffffu, sq, off);
    }
    int warp = tid >> 5, lane = tid & 31;
    if (lane == 0) { red[0][warp] = s; red[1][warp] = sq; }
    __syncthreads();
    if (warp == 0) {
        float a = (lane < 8) ? red[0][lane] : 0.f;
        float c = (lane < 8) ? red[1][lane] : 0.f;
        for (int off = 4; off > 0; off >>= 1) {
            a += __shfl_xor_sync(0xffffffffu, a, off);
            c += __shfl_xor_sync(0xffffffffu, c, off);
        }
        if (lane == 0) { red[0][0] = a; red[1][0] = c; }
    }
    __syncthreads();
    float mu  = red[0][0] * (1.f / DIM);
    float var = red[1][0] * (1.f / DIM) - mu * mu;
    float rs  = rsqrtf(var + 1e-5f);
    const float4* w4 = reinterpret_cast<const float4*>(w);
    const float4* b4 = reinterpret_cast<const float4*>(b);
    float4 ww = w4[tid], bb = b4[tid];
    float o[4];
    o[0] = (v.x - mu) * rs * ww.x + bb.x;
    o[1] = (v.y - mu) * rs * ww.y + bb.y;
    o[2] = (v.z - mu) * rs * ww.z + bb.z;
    o[3] = (v.w - mu) * rs * ww.w + bb.w;
    fp16 h[4], l[4];
    #pragma unroll
    for (int i = 0; i < 4; i++) split_fp16(o[i], h[i], l[i]);
    __half2* hp = reinterpret_cast<__half2*>(xnh + (size_t)row * DIM + tid * 4);
    __half2* lp = reinterpret_cast<__half2*>(xnl + (size_t)row * DIM + tid * 4);
    hp[0] = __half2(h[0], h[1]); hp[1] = __half2(h[2], h[3]);
    lp[0] = __half2(l[0], l[1]); lp[1] = __half2(l[2], l[3]);
}

// ---------------- xproj split-K: partial + reduce(+dtr split) ---------------
__global__ void xproj_partial(const float* __restrict__ Au, const float* __restrict__ W,
                              float* __restrict__ part) {
    __shared__ float As[32][33];
    __shared__ float Ws[32][97];
    int tid = threadIdx.x;
    int m0 = blockIdx.x * 32;
    int split = blockIdx.y;
    int kbase = split * (DI / NSPLIT);
    int tx = tid & 15, ty = tid >> 4;
    float acc[2][6];
    #pragma unroll
    for (int i = 0; i < 2; i++)
        #pragma unroll
        for (int j = 0; j < 6; j++) acc[i][j] = 0.f;

    for (int k0 = 0; k0 < DI / NSPLIT; k0 += 32) {
        {
            int row = tid >> 3, j = tid & 7;
            float4 v = *reinterpret_cast<const float4*>(&Au[(size_t)(m0 + row) * DI + kbase + k0 + j * 4]);
            As[j*4+0][row] = v.x; As[j*4+1][row] = v.y;
            As[j*4+2][row] = v.z; As[j*4+3][row] = v.w;
        }
        #pragma unroll
        for (int it = 0; it < 3; it++) {
            int i = tid + it * 256;
            int row = i >> 3, j = i & 7;
            float4 v = *reinterpret_cast<const float4*>(&W[(size_t)row * DI + kbase + k0 + j * 4]);
            Ws[j*4+0][row] = v.x; Ws[j*4+1][row] = v.y;
            Ws[j*4+2][row] = v.z; Ws[j*4+3][row] = v.w;
        }
        __syncthreads();
        #pragma unroll
        for (int kk = 0; kk < 32; kk++) {
            float a0 = As[kk][ty * 2 + 0], a1 = As[kk][ty * 2 + 1];
            float w[6];
            #pragma unroll
            for (int j = 0; j < 6; j++) w[j] = Ws[kk][tx * 6 + j];
            #pragma unroll
            for (int j = 0; j < 6; j++) {
                acc[0][j] = fmaf(a0, w[j], acc[0][j]);
                acc[1][j] = fmaf(a1, w[j], acc[1][j]);
            }
        }
        __syncthreads();
    }
    float* dst = part + (size_t)split * MROWS * XPROJ_N;
    #pragma unroll
    for (int i = 0; i < 2; i++)
        #pragma unroll
        for (int j = 0; j < 6; j++)
            dst[(size_t)(m0 + ty * 2 + i) * XPROJ_N + tx * 6 + j] = acc[i][j];
}

// reduce over splits; cols<64 also emit dt_r hi/lo fp16 (packed ld=64)
__global__ void xproj_reduce(const float* __restrict__ part, float* __restrict__ xdbl,
                             fp16* __restrict__ dtrh, fp16* __restrict__ dtrl) {
    int i = blockIdx.x * blockDim.x + threadIdx.x;   // over MROWS*24 float4s
    const int TOT4 = MROWS * XPROJ_N / 4;
    if (i >= TOT4) return;
    float4 s = reinterpret_cast<const float4*>(part)[i];
    #pragma unroll
    for (int sp = 1; sp < NSPLIT; sp++) {
        float4 v = reinterpret_cast<const float4*>(part + (size_t)sp * MROWS * XPROJ_N)[i];
        s.x += v.x; s.y += v.y; s.z += v.z; s.w += v.w;
    }
    reinterpret_cast<float4*>(xdbl)[i] = s;
    int row = i / 24, c4 = (i % 24) * 4;
    if (c4 < DTRANK) {
        float v[4] = {s.x, s.y, s.z, s.w};
        fp16 h[4], l[4];
        #pragma unroll
        for (int k = 0; k < 4; k++) split_fp16(v[k], h[k], l[k]);
        __half2* hp = reinterpret_cast<__half2*>(dtrh + (size_t)row * DTRANK + c4);
        __half2* lp = reinterpret_cast<__half2*>(dtrl + (size_t)row * DTRANK + c4);
        hp[0] = __half2(h[0], h[1]); hp[1] = __half2(h[2], h[3]);
        lp[0] = __half2(l[0], l[1]); lp[1] = __half2(l[2], l[3]);
    }
}

// ---------------- causal depthwise conv (k=4) + SiLU ------------------------
__global__ void conv_silu_kernel(const float* __restrict__ xz,
                                 const float* __restrict__ cw,
                                 const float* __restrict__ cb,
                                 float* __restrict__ u) {
    int idx = blockIdx.x * blockDim.x + threadIdx.x;
    if (idx >= BB * LL * DI) return;
    int e = idx & (DI - 1);
    int l = (idx >> 11) & (LL - 1);
    int b = idx >> 21;
    float acc = cb[e];
    #pragma unroll
    for (int k = 0; k < 4; k++) {
        int ls = l + k - 3;
        if (ls >= 0)
            acc = fmaf(cw[e * 4 + k], xz[((size_t)(b * LL + ls)) * (2 * DI) + e], acc);
    }
    float s = acc / (1.f + __expf(-acc));
    u[(size_t)(b * LL + l) * DI + e] = s;
}

// ---------------- SSM selective scan (writes y as fp16 hi/lo) ---------------
#define CHUNK 64
__global__ void scan_kernel(const float* __restrict__ dt,
                            const float* __restrict__ u,
                            const float* __restrict__ xdbl,
                            const float* __restrict__ xz,
                            const float* __restrict__ a_log,
                            const float* __restrict__ d_skip,
                            fp16* __restrict__ yh, fp16* __restrict__ yl) {
    __shared__ float sB [CHUNK][DSTATE];
    __shared__ float sC [CHUNK][DSTATE];
    __shared__ float sDt[CHUNK][16];
    __shared__ float sU [CHUNK][16];
    __shared__ float sZ [CHUNK][16];
    int tid  = threadIdx.x;
    int g    = tid >> 4;
    int lane = tid & 15;
    int c0   = blockIdx.x * 16;
    int b    = c0 >> 11;
    int e0   = c0 & (DI - 1);
    int e    = e0 + g;
    float A_n = -__expf(a_log[e * DSTATE + lane]);
    float dsk = d_skip[e];
    float h = 0.f;
    int rowbase = b * LL;
    for (int l0 = 0; l0 < LL; l0 += CHUNK) {
        __syncthreads();
        for (int i = tid; i < CHUNK * 2 * DSTATE; i += 256) {
            int r = i >> 5, j = i & 31;
            float v = xdbl[(size_t)(rowbase + l0 + r) * XPROJ_N + DTRANK + j];
            if (j < DSTATE) sB[r][j] = v; else sC[r][j - DSTATE] = v;
        }
        for (int i = tid; i < CHUNK * 16; i += 256) {
            int r = i >> 4, j = i & 15;
            size_t m = (size_t)(rowbase + l0 + r);
            sDt[r][j] = dt[m * DI + e0 + j];
            sU [r][j] = u [m * DI + e0 + j];
            sZ [r][j] = xz[m * (2 * DI) + DI + e0 + j];
        }
        __syncthreads();
        #pragma unroll 4
        for (int r = 0; r < CHUNK; r++) {
            float dtv = sDt[r][g];
            float uv  = sU [r][g];
            float dA  = __expf(dtv * A_n);
            float dBu = dtv * sB[r][lane] * uv;
            h = fmaf(dA, h, dBu);
            float yv = h * sC[r][lane];
            yv += __shfl_xor_sync(0xffffffffu, yv, 8);
            yv += __shfl_xor_sync(0xffffffffu, yv, 4);
            yv += __shfl_xor_sync(0xffffffffu, yv, 2);
            yv += __shfl_xor_sync(0xffffffffu, yv, 1);
            if (lane == 0) {
                float zv = sZ[r][g];
                float sz = zv / (1.f + __expf(-zv));
                float yo = (yv + uv * dsk) * sz;
                fp16 hh, ll;
                split_fp16(yo, hh, ll);
                size_t o = (size_t)(rowbase + l0 + r) * DI + e;
                yh[o] = hh; yl[o] = ll;
            }
        }
    }
}

// ---------------- launch -----------------------------------------------------
extern "C" void kernel_launch(void* const* d_in, const int* in_sizes, int n_in,
                              void* d_out, int out_size) {
    const float* x      = (const float*)d_in[0];
    const float* ln_w   = (const float*)d_in[1];
    const float* ln_b   = (const float*)d_in[2];
    const float* w_in   = (const float*)d_in[3];
    const float* conv_w = (const float*)d_in[4];
    const float* conv_b = (const float*)d_in[5];
    const float* w_xpr  = (const float*)d_in[6];
    const float* w_dt   = (const float*)d_in[7];
    const float* b_dt   = (const float*)d_in[8];
    const float* a_log  = (const float*)d_in[9];
    const float* d_skip = (const float*)d_in[10];
    const float* w_out  = (const float*)d_in[11];
    float* out = (float*)d_out;

    float *xz, *u, *xdbl, *dt, *part;
    fp16 *xnh, *xnl, *winh, *yh, *yl, *woh, *dtrh, *dtrl, *wdth;
    cudaGetSymbolAddress((void**)&xz,   g_xz);
    cudaGetSymbolAddress((void**)&u,    g_u);
    cudaGetSymbolAddress((void**)&xdbl, g_xdbl);
    cudaGetSymbolAddress((void**)&dt,   g_dt);
    cudaGetSymbolAddress((void**)&part, g_part);
    cudaGetSymbolAddress((void**)&xnh,  g_xnh);
    cudaGetSymbolAddress((void**)&xnl,  g_xnl);
    cudaGetSymbolAddress((void**)&winh, g_winh);
    cudaGetSymbolAddress((void**)&yh,   g_yh);
    cudaGetSymbolAddress((void**)&yl,   g_yl);
    cudaGetSymbolAddress((void**)&woh,  g_woh);
    cudaGetSymbolAddress((void**)&dtrh, g_dtrh);
    cudaGetSymbolAddress((void**)&dtrl, g_dtrl);
    cudaGetSymbolAddress((void**)&wdth, g_wdth);

    const int SMEM128 = 3 * 24576;   // BN=128: 72 KB, 3-stage ring
    const int SMEM64  = 3 * 20480;   // BN=64:  60 KB, 3-stage ring
    cudaFuncSetAttribute((const void*)gemm_f16<0,128>, cudaFuncAttributeMaxDynamicSharedMemorySize, SMEM128);
    cudaFuncSetAttribute((const void*)gemm_f16<1,128>, cudaFuncAttributeMaxDynamicSharedMemorySize, SMEM128);
    cudaFuncSetAttribute((const void*)gemm_f16<2,64>,  cudaFuncAttributeMaxDynamicSharedMemorySize, SMEM64);

    // 1. w_in conversion
    cvt_w16<<<(2*DI*DIM/4 + 255)/256, 256>>>(w_in, winh, 2*DI*DIM/4);
    // 2. LayerNorm (+ fp16 hi/lo split)
    ln_kernel<<<MROWS, 256>>>(x, ln_w, ln_b, xnh, xnl);
    // 3. w_out conversion
    cvt_w16<<<(DIM*DI/4 + 255)/256, 256>>>(w_out, woh, DIM*DI/4);
    // 4. xz = xn @ w_in^T   (2048 x 4096 x 1024)  [fp16 A-split mma, BN=128]
    gemm_f16<0,128><<<dim3(4096/128, MROWS/128), 256, SMEM128>>>(
        xnh, xnl, winh, xz, nullptr, DIM, 2*DI);
    // 5. u = silu(conv(xs))
    conv_silu_kernel<<<(BB*LL*DI)/256, 256>>>(xz, conv_w, conv_b, u);
    // 6. w_dt conversion
    cvt_w16<<<(DI*DTRANK/4 + 255)/256, 256>>>(w_dt, wdth, DI*DTRANK/4);
    // 7-8. x_dbl = u @ w_xproj^T  (2048 x 96 x 2048)  [split-K fp32, fused dtr]
    xproj_partial<<<dim3(MROWS/32, NSPLIT), 256>>>(u, w_xpr, part);
    xproj_reduce<<<(MROWS*XPROJ_N/4 + 255)/256, 256>>>(part, xdbl, dtrh, dtrl);
    // 9. dt = softplus(dt_r @ w_dt^T + b_dt)  (2048 x 2048 x 64)  [BN=128]
    gemm_f16<1,128><<<dim3(DI/128, MROWS/128), 256, SMEM128>>>(
        dtrh, dtrl, wdth, dt, b_dt, DTRANK, DI);
    // 10. selective scan (+ skip + gate, fp16 hi/lo split output)
    scan_kernel<<<(BB*DI)/16, 256>>>(dt, u, xdbl, xz, a_log, d_skip, yh, yl);
    // 11. out = residual + y @ w_out^T  (2048 x 1024 x 2048)  [BN=64, 256 CTAs]
    gemm_f16<2,64><<<dim3(DIM/64, MROWS/128), 256, SMEM64>>>(
        yh, yl, woh, out, x, DI, DIM);
}

// round 8
// speedup vs baseline: 2.1434x; 1.1789x over previous
#include <cuda_runtime.h>
#include <cuda_fp16.h>
#include <math.h>
#include <stdint.h>

// Problem shapes (fixed by the reference)
#define BB      2
#define LL      1024
#define DIM     1024
#define DI      2048          // d_inner
#define MROWS   (BB*LL)       // 2048
#define DTRANK  64
#define DSTATE  16
#define XPROJ_N (DTRANK + 2*DSTATE)  // 96
#define NSPLIT  8

typedef __half fp16;

// ---------------- scratch (device globals; no allocation allowed) ----------
__device__ float g_xz  [MROWS * 2 * DI];
__device__ float g_u   [MROWS * DI];
__device__ float g_xdbl[MROWS * XPROJ_N];
__device__ float g_dt  [MROWS * DI];
__device__ float g_part[NSPLIT * MROWS * XPROJ_N];

__device__ fp16 g_xnh [MROWS * DIM];
__device__ fp16 g_winh[2*DI * DIM];
__device__ fp16 g_yh  [MROWS * DI];
__device__ fp16 g_woh [DIM * DI];
__device__ fp16 g_dtrh[MROWS * DTRANK];
__device__ fp16 g_wdth[DI * DTRANK];

// =================== baseline PTX helpers (no arch-'a' features) ============
__device__ __forceinline__ uint32_t smem_u32(const void* p) {
    uint32_t a;
    asm("{ .reg .u64 t; cvta.to.shared.u64 t, %1; cvt.u32.u64 %0, t; }" : "=r"(a) : "l"(p));
    return a;
}
#define CP_ASYNC16(dst, src) \
    asm volatile("cp.async.cg.shared.global [%0], [%1], 16;" :: "r"(dst), "l"(src))
#define CP_COMMIT() asm volatile("cp.async.commit_group;" ::: "memory")
#define CP_WAIT(n)  asm volatile("cp.async.wait_group %0;" :: "n"(n) : "memory")

__device__ __forceinline__ void ldsm4(uint32_t* r, uint32_t addr) {
    asm volatile("ldmatrix.sync.aligned.m8n8.x4.shared.b16 {%0,%1,%2,%3}, [%4];"
                 : "=r"(r[0]), "=r"(r[1]), "=r"(r[2]), "=r"(r[3]) : "r"(addr));
}
__device__ __forceinline__ void mma_fp16(float* c, const uint32_t* a, const uint32_t* b) {
    asm volatile("mma.sync.aligned.m16n8k16.row.col.f32.f16.f16.f32 "
                 "{%0,%1,%2,%3}, {%4,%5,%6,%7}, {%8,%9}, {%0,%1,%2,%3};"
                 : "+f"(c[0]), "+f"(c[1]), "+f"(c[2]), "+f"(c[3])
                 : "r"(a[0]), "r"(a[1]), "r"(a[2]), "r"(a[3]), "r"(b[0]), "r"(b[1]));
}
// SW64 swizzle for 64-byte stage rows (verified conflict-free for ldsm phases)
__device__ __forceinline__ uint32_t sw64(uint32_t off) { return off ^ ((off >> 3) & 0x30); }

// =================== fp16 mma.sync GEMM: C = A @ B^T ========================
// Pure fp16 A and B (1 MMA per tile product).
// BM=128, BN in {128,64}, BK=32/stage, 3-stage cp.async ring, 8 warps,
// 2 CTAs/SM. EPI: 0 none, 1 softplus+bias, 2 +resid
template<int EPI, int BN>
__global__ void __launch_bounds__(256, 2)
gemm_f16(const fp16* __restrict__ Ah, const fp16* __restrict__ Bh,
         float* __restrict__ C, const float* __restrict__ aux,
         int K, int ldc) {
    extern __shared__ char smem[];
    const uint32_t sb = smem_u32(smem);
    constexpr int ABY = 128 * 64;            // bytes for A per stage
    constexpr int BBY = BN * 64;             // bytes for B per stage
    constexpr int STG = ABY + BBY;           // stage size
    constexpr int MT  = (BN == 128) ? 4 : 2; // m16 tiles per warp
    const int tid = threadIdx.x, wid = tid >> 5, lane = tid & 31;
    const int m0 = blockIdx.y * 128, n0 = blockIdx.x * BN;
    const int wm = (BN == 128) ? (wid >> 2) : (wid >> 1);
    const int wn = (BN == 128) ? (wid & 3)  : (wid & 1);

    float acc[MT][4][4];
    #pragma unroll
    for (int a = 0; a < MT; a++)
        #pragma unroll
        for (int b = 0; b < 4; b++)
            #pragma unroll
            for (int c = 0; c < 4; c++) acc[a][b][c] = 0.f;

    // stage s: [Ah | Bh], 64B SW64 rows of 32 fp16
    auto load_stage = [&](int s, int kc) {
        uint32_t base = sb + s * STG;
        #pragma unroll
        for (int it = 0; it < 2; it++) {          // A: 128 rows
            int i = tid + it * 256;
            int row = i >> 2, j = i & 3;
            uint32_t so = sw64(row * 64 + j * 16);
            CP_ASYNC16(base + so,
                       Ah + (size_t)(m0 + row) * K + kc * 32 + j * 8);
        }
        #pragma unroll
        for (int it = 0; it < BN / 64; it++) {    // B: BN rows
            int i = tid + it * 256;
            int row = i >> 2, j = i & 3;
            uint32_t so = sw64(row * 64 + j * 16);
            CP_ASYNC16(base + ABY + so,
                       Bh + (size_t)(n0 + row) * K + kc * 32 + j * 8);
        }
        CP_COMMIT();
    };

    auto compute = [&](int s) {
        uint32_t pAh = sb + s * STG;
        uint32_t pBh = pAh + ABY;
        #pragma unroll
        for (int kk = 0; kk < 2; kk++) {
            uint32_t bh[2][4];
            int grp = lane >> 3, l8 = lane & 7;
            int kbB = kk * 32 + ((grp & 1) << 4);
            #pragma unroll
            for (int pr = 0; pr < 2; pr++) {
                int row = wn * 32 + pr * 16 + ((grp >> 1) << 3) + l8;
                ldsm4(bh[pr], pBh + sw64(row * 64 + kbB));
            }
            int kbA = kk * 32 + ((lane >> 4) << 4);
            #pragma unroll
            for (int mt = 0; mt < MT; mt++) {
                uint32_t ah[4];
                int row = wm * (MT * 16) + mt * 16 + (lane & 15);
                ldsm4(ah, pAh + sw64(row * 64 + kbA));
                #pragma unroll
                for (int pr = 0; pr < 2; pr++)
                    #pragma unroll
                    for (int half = 0; half < 2; half++)
                        mma_fp16(acc[mt][pr * 2 + half], ah, &bh[pr][half * 2]);
            }
        }
    };

    const int nst = K >> 5;
    load_stage(0, 0);
    if (nst > 1) load_stage(1, 1);
    int slot = 0;
    for (int kc = 0; kc < nst; kc++) {
        if (kc + 1 < nst) CP_WAIT(1); else CP_WAIT(0);
        __syncthreads();                       // stage kc ready, prev compute done
        if (kc + 2 < nst) load_stage((kc + 2) % 3, kc + 2);
        compute(slot);
        slot = (slot + 1 == 3) ? 0 : slot + 1;
    }

    // epilogue: write fp32 directly from fragments
    #pragma unroll
    for (int mt = 0; mt < MT; mt++) {
        #pragma unroll
        for (int nt = 0; nt < 4; nt++) {
            int row = m0 + wm * (MT * 16) + mt * 16 + (lane >> 2);
            int col = n0 + wn * 32 + nt * 8 + (lane & 3) * 2;
            float v[4] = {acc[mt][nt][0], acc[mt][nt][1], acc[mt][nt][2], acc[mt][nt][3]};
            if (EPI == 1) {
                #pragma unroll
                for (int i = 0; i < 4; i++) {
                    float t = v[i] + aux[col + (i & 1)];
                    v[i] = fmaxf(t, 0.f) + log1pf(__expf(-fabsf(t)));
                }
            } else if (EPI == 2) {
                v[0] += aux[(size_t)row * ldc + col];
                v[1] += aux[(size_t)row * ldc + col + 1];
                v[2] += aux[(size_t)(row + 8) * ldc + col];
                v[3] += aux[(size_t)(row + 8) * ldc + col + 1];
            }
            *reinterpret_cast<float2*>(&C[(size_t)row * ldc + col])       = make_float2(v[0], v[1]);
            *reinterpret_cast<float2*>(&C[(size_t)(row + 8) * ldc + col]) = make_float2(v[2], v[3]);
        }
    }
}

// ---------------- conversion kernels ---------------------------------------
__global__ void cvt_w16(const float* __restrict__ s, fp16* __restrict__ h, int n4) {
    int i = blockIdx.x * blockDim.x + threadIdx.x;
    if (i >= n4) return;
    float4 v = reinterpret_cast<const float4*>(s)[i];
    __half2* hp = reinterpret_cast<__half2*>(h);
    hp[i*2]   = __floats2half2_rn(v.x, v.y);
    hp[i*2+1] = __floats2half2_rn(v.z, v.w);
}

// ---------------- LayerNorm (fp16 output) -----------------------------------
__global__ void ln_kernel(const float* __restrict__ x,
                          const float* __restrict__ w,
                          const float* __restrict__ b,
                          fp16* __restrict__ xnh) {
    int row = blockIdx.x;
    int tid = threadIdx.x;
    const float4* xr = reinterpret_cast<const float4*>(x + row * DIM);
    float4 v = xr[tid];
    float s  = v.x + v.y + v.z + v.w;
    float sq = v.x*v.x + v.y*v.y + v.z*v.z + v.w*v.w;
    __shared__ float red[2][8];
    for (int off = 16; off > 0; off >>= 1) {
        s  += __shfl_xor_sync(0xffffffffu, s,  off);
        sq += __shfl_xor_sync(0xffffffffu, sq, off);
    }
    int warp = tid >> 5, lane = tid & 31;
    if (lane == 0) { red[0][warp] = s; red[1][warp] = sq; }
    __syncthreads();
    if (warp == 0) {
        float a = (lane < 8) ? red[0][lane] : 0.f;
        float c = (lane < 8) ? red[1][lane] : 0.f;
        for (int off = 4; off > 0; off >>= 1) {
            a += __shfl_xor_sync(0xffffffffu, a, off);
            c += __shfl_xor_sync(0xffffffffu, c, off);
        }
        if (lane == 0) { red[0][0] = a; red[1][0] = c; }
    }
    __syncthreads();
    float mu  = red[0][0] * (1.f / DIM);
    float var = red[1][0] * (1.f / DIM) - mu * mu;
    float rs  = rsqrtf(var + 1e-5f);
    const float4* w4 = reinterpret_cast<const float4*>(w);
    const float4* b4 = reinterpret_cast<const float4*>(b);
    float4 ww = w4[tid], bb = b4[tid];
    float o0 = (v.x - mu) * rs * ww.x + bb.x;
    float o1 = (v.y - mu) * rs * ww.y + bb.y;
    float o2 = (v.z - mu) * rs * ww.z + bb.z;
    float o3 = (v.w - mu) * rs * ww.w + bb.w;
    __half2* hp = reinterpret_cast<__half2*>(xnh + (size_t)row * DIM + tid * 4);
    hp[0] = __floats2half2_rn(o0, o1);
    hp[1] = __floats2half2_rn(o2, o3);
}

// ---------------- xproj split-K: partial + reduce(+dtr fp16) ----------------
__global__ void xproj_partial(const float* __restrict__ Au, const float* __restrict__ W,
                              float* __restrict__ part) {
    __shared__ float As[32][33];
    __shared__ float Ws[32][97];
    int tid = threadIdx.x;
    int m0 = blockIdx.x * 32;
    int split = blockIdx.y;
    int kbase = split * (DI / NSPLIT);
    int tx = tid & 15, ty = tid >> 4;
    float acc[2][6];
    #pragma unroll
    for (int i = 0; i < 2; i++)
        #pragma unroll
        for (int j = 0; j < 6; j++) acc[i][j] = 0.f;

    for (int k0 = 0; k0 < DI / NSPLIT; k0 += 32) {
        {
            int row = tid >> 3, j = tid & 7;
            float4 v = *reinterpret_cast<const float4*>(&Au[(size_t)(m0 + row) * DI + kbase + k0 + j * 4]);
            As[j*4+0][row] = v.x; As[j*4+1][row] = v.y;
            As[j*4+2][row] = v.z; As[j*4+3][row] = v.w;
        }
        #pragma unroll
        for (int it = 0; it < 3; it++) {
            int i = tid + it * 256;
            int row = i >> 3, j = i & 7;
            float4 v = *reinterpret_cast<const float4*>(&W[(size_t)row * DI + kbase + k0 + j * 4]);
            Ws[j*4+0][row] = v.x; Ws[j*4+1][row] = v.y;
            Ws[j*4+2][row] = v.z; Ws[j*4+3][row] = v.w;
        }
        __syncthreads();
        #pragma unroll
        for (int kk = 0; kk < 32; kk++) {
            float a0 = As[kk][ty * 2 + 0], a1 = As[kk][ty * 2 + 1];
            float w[6];
            #pragma unroll
            for (int j = 0; j < 6; j++) w[j] = Ws[kk][tx * 6 + j];
            #pragma unroll
            for (int j = 0; j < 6; j++) {
                acc[0][j] = fmaf(a0, w[j], acc[0][j]);
                acc[1][j] = fmaf(a1, w[j], acc[1][j]);
            }
        }
        __syncthreads();
    }
    float* dst = part + (size_t)split * MROWS * XPROJ_N;
    #pragma unroll
    for (int i = 0; i < 2; i++)
        #pragma unroll
        for (int j = 0; j < 6; j++)
            dst[(size_t)(m0 + ty * 2 + i) * XPROJ_N + tx * 6 + j] = acc[i][j];
}

// reduce over splits; cols<64 also emit dt_r fp16 (packed ld=64)
__global__ void xproj_reduce(const float* __restrict__ part, float* __restrict__ xdbl,
                             fp16* __restrict__ dtrh) {
    int i = blockIdx.x * blockDim.x + threadIdx.x;   // over MROWS*24 float4s
    const int TOT4 = MROWS * XPROJ_N / 4;
    if (i >= TOT4) return;
    float4 s = reinterpret_cast<const float4*>(part)[i];
    #pragma unroll
    for (int sp = 1; sp < NSPLIT; sp++) {
        float4 v = reinterpret_cast<const float4*>(part + (size_t)sp * MROWS * XPROJ_N)[i];
        s.x += v.x; s.y += v.y; s.z += v.z; s.w += v.w;
    }
    reinterpret_cast<float4*>(xdbl)[i] = s;
    int row = i / 24, c4 = (i % 24) * 4;
    if (c4 < DTRANK) {
        __half2* hp = reinterpret_cast<__half2*>(dtrh + (size_t)row * DTRANK + c4);
        hp[0] = __floats2half2_rn(s.x, s.y);
        hp[1] = __floats2half2_rn(s.z, s.w);
    }
}

// ---------------- causal depthwise conv (k=4) + SiLU ------------------------
__global__ void conv_silu_kernel(const float* __restrict__ xz,
                                 const float* __restrict__ cw,
                                 const float* __restrict__ cb,
                                 float* __restrict__ u) {
    int idx = blockIdx.x * blockDim.x + threadIdx.x;
    if (idx >= BB * LL * DI) return;
    int e = idx & (DI - 1);
    int l = (idx >> 11) & (LL - 1);
    int b = idx >> 21;
    float acc = cb[e];
    #pragma unroll
    for (int k = 0; k < 4; k++) {
        int ls = l + k - 3;
        if (ls >= 0)
            acc = fmaf(cw[e * 4 + k], xz[((size_t)(b * LL + ls)) * (2 * DI) + e], acc);
    }
    float s = acc / (1.f + __expf(-acc));
    u[(size_t)(b * LL + l) * DI + e] = s;
}

// ---------------- SSM selective scan (writes y as fp16) ---------------------
#define CHUNK 64
__global__ void scan_kernel(const float* __restrict__ dt,
                            const float* __restrict__ u,
                            const float* __restrict__ xdbl,
                            const float* __restrict__ xz,
                            const float* __restrict__ a_log,
                            const float* __restrict__ d_skip,
                            fp16* __restrict__ yh) {
    __shared__ float sB [CHUNK][DSTATE];
    __shared__ float sC [CHUNK][DSTATE];
    __shared__ float sDt[CHUNK][16];
    __shared__ float sU [CHUNK][16];
    __shared__ float sZ [CHUNK][16];
    int tid  = threadIdx.x;
    int g    = tid >> 4;
    int lane = tid & 15;
    int c0   = blockIdx.x * 16;
    int b    = c0 >> 11;
    int e0   = c0 & (DI - 1);
    int e    = e0 + g;
    float A_n = -__expf(a_log[e * DSTATE + lane]);
    float dsk = d_skip[e];
    float h = 0.f;
    int rowbase = b * LL;
    for (int l0 = 0; l0 < LL; l0 += CHUNK) {
        __syncthreads();
        for (int i = tid; i < CHUNK * 2 * DSTATE; i += 256) {
            int r = i >> 5, j = i & 31;
            float v = xdbl[(size_t)(rowbase + l0 + r) * XPROJ_N + DTRANK + j];
            if (j < DSTATE) sB[r][j] = v; else sC[r][j - DSTATE] = v;
        }
        for (int i = tid; i < CHUNK * 16; i += 256) {
            int r = i >> 4, j = i & 15;
            size_t m = (size_t)(rowbase + l0 + r);
            sDt[r][j] = dt[m * DI + e0 + j];
            sU [r][j] = u [m * DI + e0 + j];
            sZ [r][j] = xz[m * (2 * DI) + DI + e0 + j];
        }
        __syncthreads();
        #pragma unroll 4
        for (int r = 0; r < CHUNK; r++) {
            float dtv = sDt[r][g];
            float uv  = sU [r][g];
            float dA  = __expf(dtv * A_n);
            float dBu = dtv * sB[r][lane] * uv;
            h = fmaf(dA, h, dBu);
            float yv = h * sC[r][lane];
            yv += __shfl_xor_sync(0xffffffffu, yv, 8);
            yv += __shfl_xor_sync(0xffffffffu, yv, 4);
            yv += __shfl_xor_sync(0xffffffffu, yv, 2);
            yv += __shfl_xor_sync(0xffffffffu, yv, 1);
            if (lane == 0) {
                float zv = sZ[r][g];
                float sz = zv / (1.f + __expf(-zv));
                float yo = (yv + uv * dsk) * sz;
                yh[(size_t)(rowbase + l0 + r) * DI + e] = __float2half_rn(yo);
            }
        }
    }
}

// ---------------- launch -----------------------------------------------------
extern "C" void kernel_launch(void* const* d_in, const int* in_sizes, int n_in,
                              void* d_out, int out_size) {
    const float* x      = (const float*)d_in[0];
    const float* ln_w   = (const float*)d_in[1];
    const float* ln_b   = (const float*)d_in[2];
    const float* w_in   = (const float*)d_in[3];
    const float* conv_w = (const float*)d_in[4];
    const float* conv_b = (const float*)d_in[5];
    const float* w_xpr  = (const float*)d_in[6];
    const float* w_dt   = (const float*)d_in[7];
    const float* b_dt   = (const float*)d_in[8];
    const float* a_log  = (const float*)d_in[9];
    const float* d_skip = (const float*)d_in[10];
    const float* w_out  = (const float*)d_in[11];
    float* out = (float*)d_out;

    float *xz, *u, *xdbl, *dt, *part;
    fp16 *xnh, *winh, *yh, *woh, *dtrh, *wdth;
    cudaGetSymbolAddress((void**)&xz,   g_xz);
    cudaGetSymbolAddress((void**)&u,    g_u);
    cudaGetSymbolAddress((void**)&xdbl, g_xdbl);
    cudaGetSymbolAddress((void**)&dt,   g_dt);
    cudaGetSymbolAddress((void**)&part, g_part);
    cudaGetSymbolAddress((void**)&xnh,  g_xnh);
    cudaGetSymbolAddress((void**)&winh, g_winh);
    cudaGetSymbolAddress((void**)&yh,   g_yh);
    cudaGetSymbolAddress((void**)&woh,  g_woh);
    cudaGetSymbolAddress((void**)&dtrh, g_dtrh);
    cudaGetSymbolAddress((void**)&wdth, g_wdth);

    const int SMEM128 = 3 * 16384;   // BN=128: 48 KB, 3-stage ring
    const int SMEM64  = 3 * 12288;   // BN=64:  36 KB, 3-stage ring
    cudaFuncSetAttribute((const void*)gemm_f16<0,128>, cudaFuncAttributeMaxDynamicSharedMemorySize, SMEM128);
    cudaFuncSetAttribute((const void*)gemm_f16<1,128>, cudaFuncAttributeMaxDynamicSharedMemorySize, SMEM128);
    cudaFuncSetAttribute((const void*)gemm_f16<2,64>,  cudaFuncAttributeMaxDynamicSharedMemorySize, SMEM64);

    // 1. w_in conversion
    cvt_w16<<<(2*DI*DIM/4 + 255)/256, 256>>>(w_in, winh, 2*DI*DIM/4);
    // 2. LayerNorm (fp16 output)
    ln_kernel<<<MROWS, 256>>>(x, ln_w, ln_b, xnh);
    // 3. w_out conversion
    cvt_w16<<<(DIM*DI/4 + 255)/256, 256>>>(w_out, woh, DIM*DI/4);
    // 4. xz = xn @ w_in^T   (2048 x 4096 x 1024)  [fp16 mma, BN=128]
    gemm_f16<0,128><<<dim3(4096/128, MROWS/128), 256, SMEM128>>>(
        xnh, winh, xz, nullptr, DIM, 2*DI);
    // 5. u = silu(conv(xs))
    conv_silu_kernel<<<(BB*LL*DI)/256, 256>>>(xz, conv_w, conv_b, u);
    // 6. w_dt conversion
    cvt_w16<<<(DI*DTRANK/4 + 255)/256, 256>>>(w_dt, wdth, DI*DTRANK/4);
    // 7-8. x_dbl = u @ w_xproj^T  (2048 x 96 x 2048)  [split-K fp32, fused dtr]
    xproj_partial<<<dim3(MROWS/32, NSPLIT), 256>>>(u, w_xpr, part);
    xproj_reduce<<<(MROWS*XPROJ_N/4 + 255)/256, 256>>>(part, xdbl, dtrh);
    // 9. dt = softplus(dt_r @ w_dt^T + b_dt)  (2048 x 2048 x 64)  [BN=128]
    gemm_f16<1,128><<<dim3(DI/128, MROWS/128), 256, SMEM128>>>(
        dtrh, wdth, dt, b_dt, DTRANK, DI);
    // 10. selective scan (+ skip + gate, fp16 output)
    scan_kernel<<<(BB*DI)/16, 256>>>(dt, u, xdbl, xz, a_log, d_skip, yh);
    // 11. out = residual + y @ w_out^T  (2048 x 1024 x 2048)  [BN=64, 256 CTAs]
    gemm_f16<2,64><<<dim3(DIM/64, MROWS/128), 256, SMEM64>>>(
        yh, woh, out, x, DI, DIM);
}